// round 10
// baseline (speedup 1.0000x reference)
#include <cuda_runtime.h>
#include <cuda_bf16.h>
#include <math.h>
#include <stdint.h>

#define TT 16
#define NQ 128
#define LATC 128
#define RR 7
#define PP 49
#define CV_K 2432      // 2401 padded to mult of 32
#define X_K 1152       // 1110 padded
#define HID 384
#define EMB 256
#define D_IN 1110

// ---------------------------------------------------------------------------
// Static device scratch
// ---------------------------------------------------------------------------
__device__ float g_pyr0[TT*96*128*LATC];
__device__ float g_pyr1[TT*48*64*LATC];
__device__ float g_pyr2[TT*24*32*LATC];
__device__ float g_pyr3[TT*12*16*LATC];
__device__ __nv_bfloat16 g_tf[(size_t)4*NQ*PP*LATC];
__device__ __nv_bfloat16 g_cv[(size_t)4*TT*NQ*CV_K];
__device__ __nv_bfloat16 g_h1[(size_t)4*TT*NQ*HID];
__device__ float         g_e [(size_t)4*TT*NQ*EMB];
__device__ __nv_bfloat16 g_x [(size_t)NQ*TT*X_K];
__device__ float         g_h2[(size_t)NQ*TT*HID];
__device__ __nv_bfloat16 g_w1t[(size_t)HID*CV_K];
__device__ __nv_bfloat16 g_w2t[(size_t)EMB*HID];
__device__ __nv_bfloat16 g_u1t[(size_t)HID*X_K];
__device__ float g_te[TT*D_IN];
__device__ float g_coords[TT*NQ*2];
__device__ float g_vis [TT*NQ];
__device__ float g_conf[TT*NQ];

__device__ __forceinline__ float geluf(float x) {
    return 0.5f * x * (1.f + erff(x * 0.70710678118654752440f));
}

__device__ __forceinline__ const float* level_ptr(int l, int& Hl, int& Wl) {
    switch (l) {
        case 0: Hl = 96; Wl = 128; return g_pyr0;
        case 1: Hl = 48; Wl = 64;  return g_pyr1;
        case 2: Hl = 24; Wl = 32;  return g_pyr2;
        default:Hl = 12; Wl = 16;  return g_pyr3;
    }
}

// ---------------------------------------------------------------------------
// mma.sync / ldmatrix helpers (baseline PTX, sm_103-safe)
// ---------------------------------------------------------------------------
__device__ __forceinline__ uint32_t smem_u32(const void* p) {
    uint32_t a;
    asm("{ .reg .u64 t; cvta.to.shared.u64 t, %1; cvt.u32.u64 %0, t; }" : "=r"(a) : "l"(p));
    return a;
}
__device__ __forceinline__ void ldsm4(uint32_t* r, uint32_t a) {
    asm volatile("ldmatrix.sync.aligned.m8n8.x4.shared.b16 {%0,%1,%2,%3}, [%4];"
        : "=r"(r[0]), "=r"(r[1]), "=r"(r[2]), "=r"(r[3]) : "r"(a));
}
__device__ __forceinline__ void mma_bf16(float* d, const uint32_t* a, const uint32_t* b) {
    asm volatile("mma.sync.aligned.m16n8k16.row.col.f32.bf16.bf16.f32 "
        "{%0,%1,%2,%3},{%4,%5,%6,%7},{%8,%9},{%0,%1,%2,%3};"
        : "+f"(d[0]), "+f"(d[1]), "+f"(d[2]), "+f"(d[3])
        : "r"(a[0]), "r"(a[1]), "r"(a[2]), "r"(a[3]), "r"(b[0]), "r"(b[1]));
}

// ---------------------------------------------------------------------------
// 4x4/s4 conv + bias + channel L2 norm. Warp-per-pixel x4, block 0 also inits
// ---------------------------------------------------------------------------
__global__ __launch_bounds__(256) void k_conv(const float* __restrict__ video,
                                              const float* __restrict__ w,
                                              const float* __restrict__ b,
                                              const float* __restrict__ q) {
    __shared__ float wsm[48][LATC];
    __shared__ float bsm[LATC];
    int tid = threadIdx.x, lane = tid & 31, warp = tid >> 5;
    for (int i = tid; i < 48 * LATC; i += 256) {
        int c = i / 48, k = i % 48;
        wsm[k][c] = w[i];
    }
    if (tid < LATC) bsm[tid] = b[tid];
    if (blockIdx.x == 0) {
        for (int i = tid; i < TT * NQ; i += 256) {
            int n = i % NQ;
            g_coords[i * 2 + 0] = q[n * 3 + 1] * 0.25f;
            g_coords[i * 2 + 1] = q[n * 3 + 2] * 0.25f;
            g_vis[i]  = 0.f;
            g_conf[i] = 0.f;
        }
    }
    __syncthreads();

#pragma unroll
    for (int px = 0; px < 4; px++) {
        int pix = blockIdx.x * 32 + warp * 4 + px;
        int x = pix & 127; int r = pix >> 7; int y = r % 96; int tf = r / 96;

        float p0, p1 = 0.f;
        {
            int k = lane;
            int ci = k / 16, kk = k % 16, ky = kk / 4, kx = kk % 4;
            p0 = video[(((size_t)tf * 3 + ci) * 384 + (y * 4 + ky)) * 512 + (x * 4 + kx)];
            p0 = 2.f * (p0 * (1.f / 255.f)) - 1.f;
            if (lane < 16) {
                k = 32 + lane;
                ci = k / 16; kk = k % 16; ky = kk / 4; kx = kk % 4;
                p1 = video[(((size_t)tf * 3 + ci) * 384 + (y * 4 + ky)) * 512 + (x * 4 + kx)];
                p1 = 2.f * (p1 * (1.f / 255.f)) - 1.f;
            }
        }
        float acc[4];
#pragma unroll
        for (int j = 0; j < 4; j++) acc[j] = bsm[lane + 32 * j];
#pragma unroll
        for (int k = 0; k < 32; k++) {
            float v = __shfl_sync(0xffffffffu, p0, k);
#pragma unroll
            for (int j = 0; j < 4; j++) acc[j] = fmaf(v, wsm[k][lane + 32 * j], acc[j]);
        }
#pragma unroll
        for (int k = 0; k < 16; k++) {
            float v = __shfl_sync(0xffffffffu, p1, k);
#pragma unroll
            for (int j = 0; j < 4; j++) acc[j] = fmaf(v, wsm[32 + k][lane + 32 * j], acc[j]);
        }
        float s = acc[0] * acc[0] + acc[1] * acc[1] + acc[2] * acc[2] + acc[3] * acc[3];
#pragma unroll
        for (int o = 16; o; o >>= 1) s += __shfl_xor_sync(0xffffffffu, s, o);
        float inv = rsqrtf(fmaxf(s, 1e-12f));
        float* dst = g_pyr0 + (size_t)pix * LATC;
#pragma unroll
        for (int j = 0; j < 4; j++) dst[lane + 32 * j] = acc[j] * inv;
    }
}

// ---------------------------------------------------------------------------
// Hierarchical pools: one block = 8x8 pyr0 patch x 128ch -> l1,l2,l3 cascaded
// ---------------------------------------------------------------------------
__global__ __launch_bounds__(256) void k_pools() {
    __shared__ float sp[8 * 8 * 128];
    __shared__ float s1[4 * 4 * 128];
    __shared__ float s2[2 * 2 * 128];
    int tid = threadIdx.x;
    int bid = blockIdx.x;
    int gx = bid & 15; int r = bid >> 4; int gy = r % 12; int t = r / 12;
    int y0 = gy * 8, x0 = gx * 8;

#pragma unroll
    for (int k = 0; k < 8; k++) {
        int f4 = k * 256 + tid;
        int e = f4 << 2;
        int c = e & 127, dyx = e >> 7;
        int dy = dyx >> 3, dx = dyx & 7;
        *(float4*)&sp[e] = *(const float4*)(g_pyr0 +
            (((size_t)t * 96 + y0 + dy) * 128 + (x0 + dx)) * LATC + c);
    }
    __syncthreads();
#pragma unroll
    for (int k = 0; k < 8; k++) {
        int u = k * 256 + tid;
        int c = u & 127, pix = u >> 7;
        int ly = pix >> 2, lx = pix & 3;
        float v = 0.25f * (sp[((2*ly)*8 + 2*lx)*128 + c] + sp[((2*ly)*8 + 2*lx+1)*128 + c]
                         + sp[((2*ly+1)*8 + 2*lx)*128 + c] + sp[((2*ly+1)*8 + 2*lx+1)*128 + c]);
        s1[u] = v;
        g_pyr1[(((size_t)t * 48 + gy*4 + ly) * 64 + gx*4 + lx) * LATC + c] = v;
    }
    __syncthreads();
#pragma unroll
    for (int k = 0; k < 2; k++) {
        int u = k * 256 + tid;
        int c = u & 127, pix = u >> 7;
        int ly = pix >> 1, lx = pix & 1;
        float v = 0.25f * (s1[((2*ly)*4 + 2*lx)*128 + c] + s1[((2*ly)*4 + 2*lx+1)*128 + c]
                         + s1[((2*ly+1)*4 + 2*lx)*128 + c] + s1[((2*ly+1)*4 + 2*lx+1)*128 + c]);
        s2[u] = v;
        g_pyr2[(((size_t)t * 24 + gy*2 + ly) * 32 + gx*2 + lx) * LATC + c] = v;
    }
    __syncthreads();
    if (tid < 128) {
        float v = 0.25f * (s2[tid] + s2[128 + tid] + s2[256 + tid] + s2[384 + tid]);
        g_pyr3[(((size_t)t * 12 + gy) * 16 + gx) * LATC + tid] = v;
    }
}

// ---------------------------------------------------------------------------
// Template features -> bf16 [l][n][p][c]
// ---------------------------------------------------------------------------
__global__ __launch_bounds__(128) void k_template(const float* __restrict__ q) {
    int n = blockIdx.x, l = blockIdx.y, c = threadIdx.x;
    int Hl, Wl;
    const float* fm = level_ptr(l, Hl, Wl);
    float qf = q[n * 3 + 0];
    float inv = exp2f(-(float)l) * 0.25f;
    float cx = q[n * 3 + 1] * inv, cy = q[n * 3 + 2] * inv;
    float tpos = fminf(fmaxf(qf, 0.f), (float)(TT - 1));
    int t0 = (int)floorf(tpos);
    float wt = tpos - (float)t0;
    int t1 = min(t0 + 1, TT - 1);
    const float* f0 = fm + (size_t)t0 * Hl * Wl * LATC;
    const float* f1 = fm + (size_t)t1 * Hl * Wl * LATC;
    __nv_bfloat16* dst = g_tf + (((size_t)l * NQ + n) * PP) * LATC + c;
    for (int p = 0; p < PP; p++) {
        int h = p / RR, ww = p % RR;
        float px = fminf(fmaxf(cx + (float)(h - 3), 0.f), (float)Wl - 1.f);
        float py = fminf(fmaxf(cy + (float)(ww - 3), 0.f), (float)Hl - 1.f);
        int x0 = (int)floorf(px); float wx = px - (float)x0; int x1 = min(x0 + 1, Wl - 1);
        int y0 = (int)floorf(py); float wy = py - (float)y0; int y1 = min(y0 + 1, Hl - 1);
        int o00 = (y0 * Wl + x0) * LATC + c, o01 = (y0 * Wl + x1) * LATC + c;
        int o10 = (y1 * Wl + x0) * LATC + c, o11 = (y1 * Wl + x1) * LATC + c;
        float v = (1.f - wy) * ((1.f - wx) * f0[o00] + wx * f0[o01])
                +        wy  * ((1.f - wx) * f0[o10] + wx * f0[o11]);
        if (wt > 0.f) {
            float v1 = (1.f - wy) * ((1.f - wx) * f1[o00] + wx * f1[o01])
                     +        wy  * ((1.f - wx) * f1[o10] + wx * f1[o11]);
            v = v * (1.f - wt) + v1 * wt;
        }
        dst[p * LATC] = __float2bfloat16(v);
    }
}

// ---------------------------------------------------------------------------
// Merged prep: 3 weight transposes + 2 pads + time-embedding interp
// ---------------------------------------------------------------------------
#define PR_W1 (HID * CV_K)
#define PR_W2 (EMB * HID)
#define PR_U1 (HID * X_K)
#define PR_CV ((4 * TT * NQ) * (CV_K - 2401))
#define PR_X  ((NQ * TT) * (X_K - D_IN))
#define PR_TE (TT * D_IN)
#define PR_ALL (PR_W1 + PR_W2 + PR_U1 + PR_CV + PR_X + PR_TE)

__global__ void k_prep(const float* __restrict__ fc1_w,
                       const float* __restrict__ fc2_w,
                       const float* __restrict__ up_w1,
                       const float* __restrict__ emb) {
    int i = blockIdx.x * blockDim.x + threadIdx.x;
    if (i < PR_W1) {
        int n = i / CV_K, k = i - n * CV_K;
        g_w1t[i] = __float2bfloat16((k < 2401) ? fc1_w[(size_t)k * HID + n] : 0.f);
        return;
    }
    i -= PR_W1;
    if (i < PR_W2) {
        int n = i / HID, k = i - n * HID;
        g_w2t[i] = __float2bfloat16(fc2_w[(size_t)k * EMB + n]);
        return;
    }
    i -= PR_W2;
    if (i < PR_U1) {
        int n = i / X_K, k = i - n * X_K;
        g_u1t[i] = __float2bfloat16((k < D_IN) ? up_w1[(size_t)k * HID + n] : 0.f);
        return;
    }
    i -= PR_U1;
    if (i < PR_CV) {
        int cw = CV_K - 2401;
        int r = i / cw, c = i - r * cw;
        g_cv[(size_t)r * CV_K + 2401 + c] = __float2bfloat16(0.f);
        return;
    }
    i -= PR_CV;
    if (i < PR_X) {
        int cw = X_K - D_IN;
        int r = i / cw, c = i - r * cw;
        g_x[(size_t)r * X_K + D_IN + c] = __float2bfloat16(0.f);
        return;
    }
    i -= PR_X;
    if (i < PR_TE) {
        int t = i / D_IN, d = i % D_IN;
        float j = ((float)t + 0.5f) * (50.f / 16.f) - 0.5f;
        j = fminf(fmaxf(j, 0.f), 49.f);
        int j0 = (int)floorf(j);
        int j1 = min(j0 + 1, 49);
        float w = j - (float)j0;
        g_te[i] = emb[j0 * D_IN + d] * (1.f - w) + emb[j1 * D_IN + d] * w;
    }
}

// ---------------------------------------------------------------------------
// Fused bilinear sample + 49x49x128 correlation via mma.sync (R9 version).
// ---------------------------------------------------------------------------
#define CS 136

__global__ __launch_bounds__(256) void k_corr_mma() {
    __shared__ __nv_bfloat16 cf[64 * CS];
    __shared__ __nv_bfloat16 tf[64 * CS];
    __shared__ int   sO[PP][4];
    __shared__ float sW[PP][2];
    int n = blockIdx.x, t = blockIdx.y, l = blockIdx.z;
    int tid = threadIdx.x, lane = tid & 31, w = tid >> 5;
    int Hl, Wl;
    const float* fm = level_ptr(l, Hl, Wl);
    fm += (size_t)t * Hl * Wl * LATC;

    if (tid < PP) {
        float inv = exp2f(-(float)l);
        float cx = g_coords[(t * NQ + n) * 2 + 0] * inv;
        float cy = g_coords[(t * NQ + n) * 2 + 1] * inv;
        int h = tid / RR, ww = tid % RR;
        float px = fminf(fmaxf(cx + (float)(h - 3), 0.f), (float)Wl - 1.f);
        float py = fminf(fmaxf(cy + (float)(ww - 3), 0.f), (float)Hl - 1.f);
        int x0 = (int)floorf(px); float wx = px - (float)x0; int x1 = min(x0 + 1, Wl - 1);
        int y0 = (int)floorf(py); float wy = py - (float)y0; int y1 = min(y0 + 1, Hl - 1);
        sO[tid][0] = (y0 * Wl + x0) * LATC;
        sO[tid][1] = (y0 * Wl + x1) * LATC;
        sO[tid][2] = (y1 * Wl + x0) * LATC;
        sO[tid][3] = (y1 * Wl + x1) * LATC;
        sW[tid][0] = wx; sW[tid][1] = wy;
    }
    for (int i = tid; i < 15 * CS; i += 256) {
        cf[49 * CS + i] = __float2bfloat16(0.f);
        tf[49 * CS + i] = __float2bfloat16(0.f);
    }
    const __nv_bfloat16* tfg = g_tf + (((size_t)l * NQ + n) * PP) * LATC;
    for (int i = tid; i < PP * 16; i += 256) {
        int p = i >> 4, c8 = (i & 15) << 3;
        *(uint4*)&tf[p * CS + c8] = *(const uint4*)(tfg + p * LATC + c8);
    }
    __syncthreads();
    for (int i = tid; i < PP * 32; i += 256) {
        int p = i >> 5, c4 = (i & 31) << 2;
        float wx = sW[p][0], wy = sW[p][1];
        float w00 = (1.f - wy) * (1.f - wx), w01 = (1.f - wy) * wx;
        float w10 = wy * (1.f - wx),         w11 = wy * wx;
        float4 v00 = *(const float4*)(fm + sO[p][0] + c4);
        float4 v01 = *(const float4*)(fm + sO[p][1] + c4);
        float4 v10 = *(const float4*)(fm + sO[p][2] + c4);
        float4 v11 = *(const float4*)(fm + sO[p][3] + c4);
        float r0 = w00 * v00.x + w01 * v01.x + w10 * v10.x + w11 * v11.x;
        float r1 = w00 * v00.y + w01 * v01.y + w10 * v10.y + w11 * v11.y;
        float r2 = w00 * v00.z + w01 * v01.z + w10 * v10.z + w11 * v11.z;
        float r3 = w00 * v00.w + w01 * v01.w + w10 * v10.w + w11 * v11.w;
        __nv_bfloat162* dst = (__nv_bfloat162*)&cf[p * CS + c4];
        dst[0] = __floats2bfloat162_rn(r0, r1);
        dst[1] = __floats2bfloat162_rn(r2, r3);
    }
    __syncthreads();

    int m2 = w >> 2, nw = w & 3;
    float acc[2][2][4] = {};
#pragma unroll
    for (int ks = 0; ks < 8; ks++) {
        uint32_t b[2][2];
        {
            uint32_t rr[4];
            uint32_t addr = smem_u32(&tf[((nw << 4) + ((lane >> 4) << 3) + (lane & 7)) * CS
                                         + (ks << 4) + (((lane >> 3) & 1) << 3)]);
            ldsm4(rr, addr);
            b[0][0] = rr[0]; b[0][1] = rr[1]; b[1][0] = rr[2]; b[1][1] = rr[3];
        }
#pragma unroll
        for (int f = 0; f < 2; f++) {
            int fa = (m2 << 1) + f;
            uint32_t a[4];
            ldsm4(a, smem_u32(&cf[((fa << 4) + (lane & 15)) * CS + (ks << 4) + ((lane >> 4) << 3)]));
            mma_bf16(acc[f][0], a, b[0]);
            mma_bf16(acc[f][1], a, b[1]);
        }
    }

    __nv_bfloat16* cv = g_cv + ((size_t)((l * TT + t) * NQ + n)) * CV_K;
#pragma unroll
    for (int f = 0; f < 2; f++) {
        int m0 = ((m2 << 1) + f << 4) + (lane >> 2);
#pragma unroll
        for (int g = 0; g < 2; g++) {
            int nn = (nw << 4) + (g << 3) + ((lane & 3) << 1);
            if (nn < PP) {
                if (m0 < PP) cv[m0 * PP + nn] = __float2bfloat16(acc[f][g][0]);
                if (m0 + 8 < PP) cv[(m0 + 8) * PP + nn] = __float2bfloat16(acc[f][g][2]);
                if (nn + 1 < PP) {
                    if (m0 < PP) cv[m0 * PP + nn + 1] = __float2bfloat16(acc[f][g][1]);
                    if (m0 + 8 < PP) cv[(m0 + 8) * PP + nn + 1] = __float2bfloat16(acc[f][g][3]);
                }
            }
        }
    }
}

// ---------------------------------------------------------------------------
// bf16 mma.sync GEMM, 64x64 CTA tile for grid fill. 128 threads, 4 warps
// (2Mx2N), warp tile 32x32, BK=32, reg-prefetch double buffer.
// M,N multiples of 64; K multiple of 32.
// ---------------------------------------------------------------------------
#define GST 40

__global__ __launch_bounds__(128) void k_gemm_bf(const __nv_bfloat16* __restrict__ A,
                                                 const __nv_bfloat16* __restrict__ Bt,
                                                 const float* __restrict__ bias,
                                                 void* __restrict__ Cv,
                                                 int M, int N, int K, int act, int outbf) {
    __shared__ __nv_bfloat16 As[2][64 * GST];
    __shared__ __nv_bfloat16 Bs[2][64 * GST];
    int tid = threadIdx.x, lane = tid & 31, warp = tid >> 5;
    int wm = (warp & 1) << 5, wn = (warp >> 1) << 5;
    int row0 = blockIdx.y << 6, col0 = blockIdx.x << 6;
    const __nv_bfloat16* Ag = A  + (size_t)row0 * K;
    const __nv_bfloat16* Bg = Bt + (size_t)col0 * K;

    // each thread: 2 x 16B per 64x32 tile
    int r1 = tid >> 2, c1 = (tid & 3) << 3;
    int r2 = (tid + 128) >> 2, c2 = ((tid + 128) & 3) << 3;

    *(uint4*)(As[0] + r1 * GST + c1) = *(const uint4*)(Ag + (size_t)r1 * K + c1);
    *(uint4*)(As[0] + r2 * GST + c2) = *(const uint4*)(Ag + (size_t)r2 * K + c2);
    *(uint4*)(Bs[0] + r1 * GST + c1) = *(const uint4*)(Bg + (size_t)r1 * K + c1);
    *(uint4*)(Bs[0] + r2 * GST + c2) = *(const uint4*)(Bg + (size_t)r2 * K + c2);
    __syncthreads();

    float acc[2][4][4] = {};
    int nk = K >> 5;
    for (int i = 0; i < nk; i++) {
        int s = i & 1;
        uint4 ra0, ra1, rb0, rb1;
        bool pre = (i + 1 < nk);
        if (pre) {
            int k0 = (i + 1) << 5;
            ra0 = *(const uint4*)(Ag + (size_t)r1 * K + k0 + c1);
            ra1 = *(const uint4*)(Ag + (size_t)r2 * K + k0 + c2);
            rb0 = *(const uint4*)(Bg + (size_t)r1 * K + k0 + c1);
            rb1 = *(const uint4*)(Bg + (size_t)r2 * K + k0 + c2);
        }
#pragma unroll
        for (int ks = 0; ks < 2; ks++) {
            uint32_t b[4][2];
#pragma unroll
            for (int g = 0; g < 2; g++) {
                uint32_t rr[4];
                uint32_t addr = smem_u32(Bs[s] + (wn + (g << 4) + ((lane >> 4) << 3) + (lane & 7)) * GST
                                         + (ks << 4) + (((lane >> 3) & 1) << 3));
                ldsm4(rr, addr);
                b[g * 2][0] = rr[0]; b[g * 2][1] = rr[1];
                b[g * 2 + 1][0] = rr[2]; b[g * 2 + 1][1] = rr[3];
            }
#pragma unroll
            for (int f = 0; f < 2; f++) {
                uint32_t a[4];
                ldsm4(a, smem_u32(As[s] + (wm + (f << 4) + (lane & 15)) * GST
                                  + (ks << 4) + ((lane >> 4) << 3)));
#pragma unroll
                for (int g = 0; g < 4; g++) mma_bf16(acc[f][g], a, b[g]);
            }
        }
        if (pre) {
            int s2 = s ^ 1;
            *(uint4*)(As[s2] + r1 * GST + c1) = ra0;
            *(uint4*)(As[s2] + r2 * GST + c2) = ra1;
            *(uint4*)(Bs[s2] + r1 * GST + c1) = rb0;
            *(uint4*)(Bs[s2] + r2 * GST + c2) = rb1;
        }
        __syncthreads();
    }
#pragma unroll
    for (int f = 0; f < 2; f++) {
        int m = row0 + wm + (f << 4) + (lane >> 2);
#pragma unroll
        for (int g = 0; g < 4; g++) {
            int nn = col0 + wn + (g << 3) + ((lane & 3) << 1);
            float b0 = bias[nn], b1 = bias[nn + 1];
            float v0 = acc[f][g][0] + b0, v1 = acc[f][g][1] + b1;
            float v2 = acc[f][g][2] + b0, v3 = acc[f][g][3] + b1;
            if (act) { v0 = geluf(v0); v1 = geluf(v1); v2 = geluf(v2); v3 = geluf(v3); }
            if (outbf) {
                __nv_bfloat16* C = (__nv_bfloat16*)Cv;
                C[(size_t)m * N + nn] = __float2bfloat16(v0);
                C[(size_t)m * N + nn + 1] = __float2bfloat16(v1);
                C[(size_t)(m + 8) * N + nn] = __float2bfloat16(v2);
                C[(size_t)(m + 8) * N + nn + 1] = __float2bfloat16(v3);
            } else {
                float* C = (float*)Cv;
                C[(size_t)m * N + nn] = v0;
                C[(size_t)m * N + nn + 1] = v1;
                C[(size_t)(m + 8) * N + nn] = v2;
                C[(size_t)(m + 8) * N + nn + 1] = v3;
            }
        }
    }
}

// ---------------------------------------------------------------------------
// Assemble update-MLP input (bf16)
// ---------------------------------------------------------------------------
__global__ __launch_bounds__(128) void k_assemble() {
    int row = blockIdx.x;
    int n = row >> 4, t = row & 15;
    int tid = threadIdx.x;
    __shared__ float x4[4];
    if (tid == 0) {
        float cx = g_coords[(t * NQ + n) * 2 + 0];
        float cy = g_coords[(t * NQ + n) * 2 + 1];
        float rfx = 0.f, rfy = 0.f, rbx = 0.f, rby = 0.f;
        if (t < TT - 1) {
            rfx = (cx - g_coords[((t + 1) * NQ + n) * 2 + 0]) * (1.f / 128.f);
            rfy = (cy - g_coords[((t + 1) * NQ + n) * 2 + 1]) * (1.f / 96.f);
        }
        if (t > 0) {
            rbx = (cx - g_coords[((t - 1) * NQ + n) * 2 + 0]) * (1.f / 128.f);
            rby = (cy - g_coords[((t - 1) * NQ + n) * 2 + 1]) * (1.f / 96.f);
        }
        x4[0] = rfx; x4[1] = rfy; x4[2] = rbx; x4[3] = rby;
    }
    __syncthreads();
    __nv_bfloat16* dst = g_x + (size_t)row * X_K;
    for (int d = tid; d < D_IN; d += 128) {
        float v;
        if (d == 0) v = g_vis[t * NQ + n];
        else if (d == 1) v = g_conf[t * NQ + n];
        else if (d < 2 + 4 * EMB) {
            int qd = d - 2;
            int l = qd >> 8, k = qd & 255;
            v = g_e[(((size_t)(l * TT + t) * NQ + n) << 8) + k];
        } else {
            int j = d - (2 + 4 * EMB);
            if (j < 4) v = x4[j];
            else if (j < 44) {
                int s = (j - 4) >> 2, dd = (j - 4) & 3;
                v = sinf(x4[dd] * exp2f((float)s));
            } else {
                int s = (j - 44) >> 2, dd = (j - 44) & 3;
                v = cosf(x4[dd] * exp2f((float)s));
            }
        }
        dst[d] = __float2bfloat16(v + g_te[t * D_IN + d]);
    }
}

// ---------------------------------------------------------------------------
// Final tiny GEMV (384->4) + state update
// ---------------------------------------------------------------------------
__global__ __launch_bounds__(128) void k_update(const float* __restrict__ w2,
                                                const float* __restrict__ b2) {
    int row = blockIdx.x;
    int tid = threadIdx.x;
    const float* hrow = g_h2 + (size_t)row * HID;
    float a0 = 0.f, a1 = 0.f, a2 = 0.f, a3 = 0.f;
    for (int i = tid; i < HID; i += 128) {
        float h = hrow[i];
        const float* w = w2 + i * 4;
        a0 = fmaf(h, w[0], a0); a1 = fmaf(h, w[1], a1);
        a2 = fmaf(h, w[2], a2); a3 = fmaf(h, w[3], a3);
    }
#pragma unroll
    for (int o = 16; o; o >>= 1) {
        a0 += __shfl_xor_sync(0xffffffffu, a0, o);
        a1 += __shfl_xor_sync(0xffffffffu, a1, o);
        a2 += __shfl_xor_sync(0xffffffffu, a2, o);
        a3 += __shfl_xor_sync(0xffffffffu, a3, o);
    }
    __shared__ float red[4][4];
    int warp = tid >> 5, lane = tid & 31;
    if (lane == 0) { red[warp][0] = a0; red[warp][1] = a1; red[warp][2] = a2; red[warp][3] = a3; }
    __syncthreads();
    if (tid == 0) {
        float d0 = red[0][0] + red[1][0] + red[2][0] + red[3][0] + b2[0];
        float d1 = red[0][1] + red[1][1] + red[2][1] + red[3][1] + b2[1];
        float d2 = red[0][2] + red[1][2] + red[2][2] + red[3][2] + b2[2];
        float d3 = red[0][3] + red[1][3] + red[2][3] + red[3][3] + b2[3];
        int n = row >> 4, t = row & 15;
        g_coords[(t * NQ + n) * 2 + 0] += d0;
        g_coords[(t * NQ + n) * 2 + 1] += d1;
        g_vis[t * NQ + n]  += d2;
        g_conf[t * NQ + n] += d3;
    }
}

// ---------------------------------------------------------------------------
// Outputs
// ---------------------------------------------------------------------------
__global__ void k_output(float* __restrict__ out) {
    int i = blockIdx.x * blockDim.x + threadIdx.x;
    if (i >= 8192) return;
    if (i < 4096) out[i] = g_coords[i] * 4.f;
    else if (i < 6144) out[i] = 1.f / (1.f + expf(-g_vis[i - 4096]));
    else out[i] = 1.f / (1.f + expf(-g_conf[i - 6144]));
}

// ---------------------------------------------------------------------------
// Launch. Order: conv(1) pools(2) template(3) corr(4, profiled) prep(5) ...
// ---------------------------------------------------------------------------
extern "C" void kernel_launch(void* const* d_in, const int* in_sizes, int n_in,
                              void* d_out, int out_size) {
    const float* video   = (const float*)d_in[0];
    const float* queries = (const float*)d_in[1];
    const float* fnet_w  = (const float*)d_in[2];
    const float* fnet_b  = (const float*)d_in[3];
    const float* fc1_w   = (const float*)d_in[4];
    const float* fc1_b   = (const float*)d_in[5];
    const float* fc2_w   = (const float*)d_in[6];
    const float* fc2_b   = (const float*)d_in[7];
    const float* up_w1   = (const float*)d_in[8];
    const float* up_b1   = (const float*)d_in[9];
    const float* up_w2   = (const float*)d_in[10];
    const float* up_b2   = (const float*)d_in[11];
    const float* time_emb= (const float*)d_in[12];
    float* out = (float*)d_out;

    __nv_bfloat16 *p_cv, *p_h1, *p_x, *p_w1t, *p_w2t, *p_u1t;
    float *p_e, *p_h2;
    cudaGetSymbolAddress((void**)&p_cv,  g_cv);
    cudaGetSymbolAddress((void**)&p_h1,  g_h1);
    cudaGetSymbolAddress((void**)&p_e,   g_e);
    cudaGetSymbolAddress((void**)&p_x,   g_x);
    cudaGetSymbolAddress((void**)&p_h2,  g_h2);
    cudaGetSymbolAddress((void**)&p_w1t, g_w1t);
    cudaGetSymbolAddress((void**)&p_w2t, g_w2t);
    cudaGetSymbolAddress((void**)&p_u1t, g_u1t);

    const int M1 = 4 * TT * NQ;   // 8192
    const int M3 = NQ * TT;       // 2048

    k_conv<<<TT * 96 * 128 / 32, 256>>>(video, fnet_w, fnet_b, queries);  // 1
    k_pools<<<TT * 12 * 16, 256>>>();                                     // 2
    k_template<<<dim3(NQ, 4), 128>>>(queries);                            // 3

    for (int it = 0; it < 4; it++) {
        k_corr_mma<<<dim3(NQ, TT, 4), 256>>>();                           // 4 on it=0
        if (it == 0)
            k_prep<<<(PR_ALL + 255) / 256, 256>>>(fc1_w, fc2_w, up_w1, time_emb);
        k_gemm_bf<<<dim3(HID / 64, M1 / 64), 128>>>(p_cv, p_w1t, fc1_b, p_h1, M1, HID, CV_K, 1, 1);
        k_gemm_bf<<<dim3(EMB / 64, M1 / 64), 128>>>(p_h1, p_w2t, fc2_b, p_e, M1, EMB, HID, 0, 0);
        k_assemble<<<M3, 128>>>();
        k_gemm_bf<<<dim3(HID / 64, M3 / 64), 128>>>(p_x, p_u1t, up_b1, p_h2, M3, HID, X_K, 1, 0);
        k_update<<<M3, 128>>>(up_w2, up_b2);
    }
    k_output<<<(8192 + 255) / 256, 256>>>(out);
}

// round 11
// speedup vs baseline: 1.0414x; 1.0414x over previous
#include <cuda_runtime.h>
#include <cuda_bf16.h>
#include <math.h>
#include <stdint.h>

#define TT 16
#define NQ 128
#define LATC 128
#define RR 7
#define PP 49
#define CV_K 2432      // 2401 padded to mult of 32
#define X_K 1152       // 1110 padded
#define HID 384
#define EMB 256
#define D_IN 1110

// ---------------------------------------------------------------------------
// Static device scratch
// ---------------------------------------------------------------------------
__device__ float g_pyr0[TT*96*128*LATC];
__device__ float g_pyr1[TT*48*64*LATC];
__device__ float g_pyr2[TT*24*32*LATC];
__device__ float g_pyr3[TT*12*16*LATC];
__device__ __nv_bfloat16 g_tf[(size_t)4*NQ*PP*LATC];
__device__ __nv_bfloat16 g_cv[(size_t)4*TT*NQ*CV_K];
__device__ __nv_bfloat16 g_h1[(size_t)4*TT*NQ*HID];
__device__ float         g_e [(size_t)4*TT*NQ*EMB];
__device__ __nv_bfloat16 g_x [(size_t)NQ*TT*X_K];
__device__ float         g_h2[(size_t)NQ*TT*HID];
__device__ __nv_bfloat16 g_w1t[(size_t)HID*CV_K];
__device__ __nv_bfloat16 g_w2t[(size_t)EMB*HID];
__device__ __nv_bfloat16 g_u1t[(size_t)HID*X_K];
__device__ float g_te[TT*D_IN];
__device__ float g_coords[TT*NQ*2];
__device__ float g_vis [TT*NQ];
__device__ float g_conf[TT*NQ];

__device__ __forceinline__ float geluf(float x) {
    return 0.5f * x * (1.f + erff(x * 0.70710678118654752440f));
}

__device__ __forceinline__ const float* level_ptr(int l, int& Hl, int& Wl) {
    switch (l) {
        case 0: Hl = 96; Wl = 128; return g_pyr0;
        case 1: Hl = 48; Wl = 64;  return g_pyr1;
        case 2: Hl = 24; Wl = 32;  return g_pyr2;
        default:Hl = 12; Wl = 16;  return g_pyr3;
    }
}

// ---------------------------------------------------------------------------
// mma.sync / ldmatrix helpers (baseline PTX, sm_103-safe)
// ---------------------------------------------------------------------------
__device__ __forceinline__ uint32_t smem_u32(const void* p) {
    uint32_t a;
    asm("{ .reg .u64 t; cvta.to.shared.u64 t, %1; cvt.u32.u64 %0, t; }" : "=r"(a) : "l"(p));
    return a;
}
__device__ __forceinline__ void ldsm4(uint32_t* r, uint32_t a) {
    asm volatile("ldmatrix.sync.aligned.m8n8.x4.shared.b16 {%0,%1,%2,%3}, [%4];"
        : "=r"(r[0]), "=r"(r[1]), "=r"(r[2]), "=r"(r[3]) : "r"(a));
}
__device__ __forceinline__ void mma_bf16(float* d, const uint32_t* a, const uint32_t* b) {
    asm volatile("mma.sync.aligned.m16n8k16.row.col.f32.bf16.bf16.f32 "
        "{%0,%1,%2,%3},{%4,%5,%6,%7},{%8,%9},{%0,%1,%2,%3};"
        : "+f"(d[0]), "+f"(d[1]), "+f"(d[2]), "+f"(d[3])
        : "r"(a[0]), "r"(a[1]), "r"(a[2]), "r"(a[3]), "r"(b[0]), "r"(b[1]));
}

// ---------------------------------------------------------------------------
// 4x4/s4 conv + bias + channel L2 norm. Warp-per-pixel x4, block 0 also inits
// ---------------------------------------------------------------------------
__global__ __launch_bounds__(256) void k_conv(const float* __restrict__ video,
                                              const float* __restrict__ w,
                                              const float* __restrict__ b,
                                              const float* __restrict__ q) {
    __shared__ float wsm[48][LATC];
    __shared__ float bsm[LATC];
    int tid = threadIdx.x, lane = tid & 31, warp = tid >> 5;
    for (int i = tid; i < 48 * LATC; i += 256) {
        int c = i / 48, k = i % 48;
        wsm[k][c] = w[i];
    }
    if (tid < LATC) bsm[tid] = b[tid];
    if (blockIdx.x == 0) {
        for (int i = tid; i < TT * NQ; i += 256) {
            int n = i % NQ;
            g_coords[i * 2 + 0] = q[n * 3 + 1] * 0.25f;
            g_coords[i * 2 + 1] = q[n * 3 + 2] * 0.25f;
            g_vis[i]  = 0.f;
            g_conf[i] = 0.f;
        }
    }
    __syncthreads();

#pragma unroll
    for (int px = 0; px < 4; px++) {
        int pix = blockIdx.x * 32 + warp * 4 + px;
        int x = pix & 127; int r = pix >> 7; int y = r % 96; int tf = r / 96;

        float p0, p1 = 0.f;
        {
            int k = lane;
            int ci = k / 16, kk = k % 16, ky = kk / 4, kx = kk % 4;
            p0 = video[(((size_t)tf * 3 + ci) * 384 + (y * 4 + ky)) * 512 + (x * 4 + kx)];
            p0 = 2.f * (p0 * (1.f / 255.f)) - 1.f;
            if (lane < 16) {
                k = 32 + lane;
                ci = k / 16; kk = k % 16; ky = kk / 4; kx = kk % 4;
                p1 = video[(((size_t)tf * 3 + ci) * 384 + (y * 4 + ky)) * 512 + (x * 4 + kx)];
                p1 = 2.f * (p1 * (1.f / 255.f)) - 1.f;
            }
        }
        float acc[4];
#pragma unroll
        for (int j = 0; j < 4; j++) acc[j] = bsm[lane + 32 * j];
#pragma unroll
        for (int k = 0; k < 32; k++) {
            float v = __shfl_sync(0xffffffffu, p0, k);
#pragma unroll
            for (int j = 0; j < 4; j++) acc[j] = fmaf(v, wsm[k][lane + 32 * j], acc[j]);
        }
#pragma unroll
        for (int k = 0; k < 16; k++) {
            float v = __shfl_sync(0xffffffffu, p1, k);
#pragma unroll
            for (int j = 0; j < 4; j++) acc[j] = fmaf(v, wsm[32 + k][lane + 32 * j], acc[j]);
        }
        float s = acc[0] * acc[0] + acc[1] * acc[1] + acc[2] * acc[2] + acc[3] * acc[3];
#pragma unroll
        for (int o = 16; o; o >>= 1) s += __shfl_xor_sync(0xffffffffu, s, o);
        float inv = rsqrtf(fmaxf(s, 1e-12f));
        float* dst = g_pyr0 + (size_t)pix * LATC;
#pragma unroll
        for (int j = 0; j < 4; j++) dst[lane + 32 * j] = acc[j] * inv;
    }
}

// ---------------------------------------------------------------------------
// Hierarchical pools: one block = 8x8 pyr0 patch x 128ch -> l1,l2,l3 cascaded
// ---------------------------------------------------------------------------
__global__ __launch_bounds__(256) void k_pools() {
    __shared__ float sp[8 * 8 * 128];
    __shared__ float s1[4 * 4 * 128];
    __shared__ float s2[2 * 2 * 128];
    int tid = threadIdx.x;
    int bid = blockIdx.x;
    int gx = bid & 15; int r = bid >> 4; int gy = r % 12; int t = r / 12;
    int y0 = gy * 8, x0 = gx * 8;

#pragma unroll
    for (int k = 0; k < 8; k++) {
        int f4 = k * 256 + tid;
        int e = f4 << 2;
        int c = e & 127, dyx = e >> 7;
        int dy = dyx >> 3, dx = dyx & 7;
        *(float4*)&sp[e] = *(const float4*)(g_pyr0 +
            (((size_t)t * 96 + y0 + dy) * 128 + (x0 + dx)) * LATC + c);
    }
    __syncthreads();
#pragma unroll
    for (int k = 0; k < 8; k++) {
        int u = k * 256 + tid;
        int c = u & 127, pix = u >> 7;
        int ly = pix >> 2, lx = pix & 3;
        float v = 0.25f * (sp[((2*ly)*8 + 2*lx)*128 + c] + sp[((2*ly)*8 + 2*lx+1)*128 + c]
                         + sp[((2*ly+1)*8 + 2*lx)*128 + c] + sp[((2*ly+1)*8 + 2*lx+1)*128 + c]);
        s1[u] = v;
        g_pyr1[(((size_t)t * 48 + gy*4 + ly) * 64 + gx*4 + lx) * LATC + c] = v;
    }
    __syncthreads();
#pragma unroll
    for (int k = 0; k < 2; k++) {
        int u = k * 256 + tid;
        int c = u & 127, pix = u >> 7;
        int ly = pix >> 1, lx = pix & 1;
        float v = 0.25f * (s1[((2*ly)*4 + 2*lx)*128 + c] + s1[((2*ly)*4 + 2*lx+1)*128 + c]
                         + s1[((2*ly+1)*4 + 2*lx)*128 + c] + s1[((2*ly+1)*4 + 2*lx+1)*128 + c]);
        s2[u] = v;
        g_pyr2[(((size_t)t * 24 + gy*2 + ly) * 32 + gx*2 + lx) * LATC + c] = v;
    }
    __syncthreads();
    if (tid < 128) {
        float v = 0.25f * (s2[tid] + s2[128 + tid] + s2[256 + tid] + s2[384 + tid]);
        g_pyr3[(((size_t)t * 12 + gy) * 16 + gx) * LATC + tid] = v;
    }
}

// ---------------------------------------------------------------------------
// Template features -> bf16 [l][n][p][c]
// ---------------------------------------------------------------------------
__global__ __launch_bounds__(128) void k_template(const float* __restrict__ q) {
    int n = blockIdx.x, l = blockIdx.y, c = threadIdx.x;
    int Hl, Wl;
    const float* fm = level_ptr(l, Hl, Wl);
    float qf = q[n * 3 + 0];
    float inv = exp2f(-(float)l) * 0.25f;
    float cx = q[n * 3 + 1] * inv, cy = q[n * 3 + 2] * inv;
    float tpos = fminf(fmaxf(qf, 0.f), (float)(TT - 1));
    int t0 = (int)floorf(tpos);
    float wt = tpos - (float)t0;
    int t1 = min(t0 + 1, TT - 1);
    const float* f0 = fm + (size_t)t0 * Hl * Wl * LATC;
    const float* f1 = fm + (size_t)t1 * Hl * Wl * LATC;
    __nv_bfloat16* dst = g_tf + (((size_t)l * NQ + n) * PP) * LATC + c;
    for (int p = 0; p < PP; p++) {
        int h = p / RR, ww = p % RR;
        float px = fminf(fmaxf(cx + (float)(h - 3), 0.f), (float)Wl - 1.f);
        float py = fminf(fmaxf(cy + (float)(ww - 3), 0.f), (float)Hl - 1.f);
        int x0 = (int)floorf(px); float wx = px - (float)x0; int x1 = min(x0 + 1, Wl - 1);
        int y0 = (int)floorf(py); float wy = py - (float)y0; int y1 = min(y0 + 1, Hl - 1);
        int o00 = (y0 * Wl + x0) * LATC + c, o01 = (y0 * Wl + x1) * LATC + c;
        int o10 = (y1 * Wl + x0) * LATC + c, o11 = (y1 * Wl + x1) * LATC + c;
        float v = (1.f - wy) * ((1.f - wx) * f0[o00] + wx * f0[o01])
                +        wy  * ((1.f - wx) * f0[o10] + wx * f0[o11]);
        if (wt > 0.f) {
            float v1 = (1.f - wy) * ((1.f - wx) * f1[o00] + wx * f1[o01])
                     +        wy  * ((1.f - wx) * f1[o10] + wx * f1[o11]);
            v = v * (1.f - wt) + v1 * wt;
        }
        dst[p * LATC] = __float2bfloat16(v);
    }
}

// ---------------------------------------------------------------------------
// Merged prep: 3 weight transposes + 2 pads + time-embedding interp
// ---------------------------------------------------------------------------
#define PR_W1 (HID * CV_K)
#define PR_W2 (EMB * HID)
#define PR_U1 (HID * X_K)
#define PR_CV ((4 * TT * NQ) * (CV_K - 2401))
#define PR_X  ((NQ * TT) * (X_K - D_IN))
#define PR_TE (TT * D_IN)
#define PR_ALL (PR_W1 + PR_W2 + PR_U1 + PR_CV + PR_X + PR_TE)

__global__ void k_prep(const float* __restrict__ fc1_w,
                       const float* __restrict__ fc2_w,
                       const float* __restrict__ up_w1,
                       const float* __restrict__ emb) {
    int i = blockIdx.x * blockDim.x + threadIdx.x;
    if (i < PR_W1) {
        int n = i / CV_K, k = i - n * CV_K;
        g_w1t[i] = __float2bfloat16((k < 2401) ? fc1_w[(size_t)k * HID + n] : 0.f);
        return;
    }
    i -= PR_W1;
    if (i < PR_W2) {
        int n = i / HID, k = i - n * HID;
        g_w2t[i] = __float2bfloat16(fc2_w[(size_t)k * EMB + n]);
        return;
    }
    i -= PR_W2;
    if (i < PR_U1) {
        int n = i / X_K, k = i - n * X_K;
        g_u1t[i] = __float2bfloat16((k < D_IN) ? up_w1[(size_t)k * HID + n] : 0.f);
        return;
    }
    i -= PR_U1;
    if (i < PR_CV) {
        int cw = CV_K - 2401;
        int r = i / cw, c = i - r * cw;
        g_cv[(size_t)r * CV_K + 2401 + c] = __float2bfloat16(0.f);
        return;
    }
    i -= PR_CV;
    if (i < PR_X) {
        int cw = X_K - D_IN;
        int r = i / cw, c = i - r * cw;
        g_x[(size_t)r * X_K + D_IN + c] = __float2bfloat16(0.f);
        return;
    }
    i -= PR_X;
    if (i < PR_TE) {
        int t = i / D_IN, d = i % D_IN;
        float j = ((float)t + 0.5f) * (50.f / 16.f) - 0.5f;
        j = fminf(fmaxf(j, 0.f), 49.f);
        int j0 = (int)floorf(j);
        int j1 = min(j0 + 1, 49);
        float w = j - (float)j0;
        g_te[i] = emb[j0 * D_IN + d] * (1.f - w) + emb[j1 * D_IN + d] * w;
    }
}

// ---------------------------------------------------------------------------
// Fused bilinear sample + 49x49x128 correlation via mma.sync.
// Footprint optimization: 8x8 pixel neighborhood streamed into smem (fp32,
// coalesced), bilinear from smem. Template prefetched to regs, STS'd into
// the footprint space after interpolation (smem reuse).
// Dynamic smem: fp 32KB (-> tf 17KB) + cf 17KB = 50176 B.
// ---------------------------------------------------------------------------
#define CS 136
#define CORR_DSM (8 * 8 * 128 * 4 + 64 * CS * 2)

__global__ __launch_bounds__(256) void k_corr_mma() {
    extern __shared__ char cdsm[];
    float*         fp = (float*)cdsm;                 // 32 KB footprint (fp32)
    __nv_bfloat16* tf = (__nv_bfloat16*)cdsm;         // overlays fp after interp
    __nv_bfloat16* cf = (__nv_bfloat16*)(cdsm + 8 * 8 * 128 * 4);
    __shared__ int   sO[PP][4];
    __shared__ float sW[PP][2];
    int n = blockIdx.x, t = blockIdx.y, l = blockIdx.z;
    int tid = threadIdx.x, lane = tid & 31, w = tid >> 5;
    int Hl, Wl;
    const float* fm = level_ptr(l, Hl, Wl);
    fm += (size_t)t * Hl * Wl * LATC;

    // footprint origin (all threads compute identically)
    float linv = exp2f(-(float)l);
    float cx = g_coords[(t * NQ + n) * 2 + 0] * linv;
    float cy = g_coords[(t * NQ + n) * 2 + 1] * linv;
    int x_base = min(max((int)floorf(fminf(fmaxf(cx - 3.f, 0.f), (float)Wl - 1.f)), 0), Wl - 8);
    int y_base = min(max((int)floorf(fminf(fmaxf(cy - 3.f, 0.f), (float)Hl - 1.f)), 0), Hl - 8);

    // prefetch template tile into registers (196 threads x uint4)
    const __nv_bfloat16* tfg = g_tf + (((size_t)l * NQ + n) * PP) * LATC;
    uint4 treg0 = make_uint4(0, 0, 0, 0);
    if (tid < 196) {
        int p = tid >> 2, c32 = (tid & 3) << 5;   // 4 x uint4 per row? no: 16 uint4/row
        (void)p; (void)c32;
    }
    // 49 rows x 16 uint4 = 784 uint4; 256 threads: 3-4 each -> keep 4 regs
    uint4 tr[4] = {make_uint4(0,0,0,0), make_uint4(0,0,0,0), make_uint4(0,0,0,0), make_uint4(0,0,0,0)};
#pragma unroll
    for (int k = 0; k < 4; k++) {
        int i = k * 256 + tid;
        if (i < PP * 16) {
            int p = i >> 4, c8 = (i & 15) << 3;
            tr[k] = *(const uint4*)(tfg + p * LATC + c8);
        }
    }
    (void)treg0;

    // per-position offsets into footprint
    if (tid < PP) {
        int h = tid / RR, ww = tid % RR;
        float px = fminf(fmaxf(cx + (float)(h - 3), 0.f), (float)Wl - 1.f);
        float py = fminf(fmaxf(cy + (float)(ww - 3), 0.f), (float)Hl - 1.f);
        int x0 = (int)floorf(px); float wx = px - (float)x0; int x1 = min(x0 + 1, Wl - 1);
        int y0 = (int)floorf(py); float wy = py - (float)y0; int y1 = min(y0 + 1, Hl - 1);
        int sx0 = x0 - x_base, sx1 = x1 - x_base;
        int sy0 = y0 - y_base, sy1 = y1 - y_base;
        sO[tid][0] = ((sy0 << 3) + sx0) << 7;
        sO[tid][1] = ((sy0 << 3) + sx1) << 7;
        sO[tid][2] = ((sy1 << 3) + sx0) << 7;
        sO[tid][3] = ((sy1 << 3) + sx1) << 7;
        sW[tid][0] = wx; sW[tid][1] = wy;
    }
    // zero cf pad rows 49-63
    for (int i = tid; i < 15 * CS; i += 256)
        cf[49 * CS + i] = __float2bfloat16(0.f);

    // stream footprint (8x8 pixels x 128 ch fp32, coalesced)
#pragma unroll
    for (int k = 0; k < 8; k++) {
        int i = k * 256 + tid;              // [0, 2048) float4 units
        int c4 = (i & 31) << 2, pix = i >> 5;
        int dy = pix >> 3, dx = pix & 7;
        *(float4*)&fp[(pix << 7) + c4] =
            *(const float4*)(fm + ((y_base + dy) * Wl + x_base + dx) * LATC + c4);
    }
    __syncthreads();

    // bilinear interp from smem footprint -> cf (bf16)
    for (int i = tid; i < PP * 32; i += 256) {
        int p = i >> 5, c4 = (i & 31) << 2;
        float wx = sW[p][0], wy = sW[p][1];
        float w00 = (1.f - wy) * (1.f - wx), w01 = (1.f - wy) * wx;
        float w10 = wy * (1.f - wx),         w11 = wy * wx;
        float4 v00 = *(const float4*)&fp[sO[p][0] + c4];
        float4 v01 = *(const float4*)&fp[sO[p][1] + c4];
        float4 v10 = *(const float4*)&fp[sO[p][2] + c4];
        float4 v11 = *(const float4*)&fp[sO[p][3] + c4];
        float r0 = w00 * v00.x + w01 * v01.x + w10 * v10.x + w11 * v11.x;
        float r1 = w00 * v00.y + w01 * v01.y + w10 * v10.y + w11 * v11.y;
        float r2 = w00 * v00.z + w01 * v01.z + w10 * v10.z + w11 * v11.z;
        float r3 = w00 * v00.w + w01 * v01.w + w10 * v10.w + w11 * v11.w;
        __nv_bfloat162* dst = (__nv_bfloat162*)&cf[p * CS + c4];
        dst[0] = __floats2bfloat162_rn(r0, r1);
        dst[1] = __floats2bfloat162_rn(r2, r3);
    }
    __syncthreads();   // footprint dead; reuse as tf

    // store template regs into tf region + zero pad rows
#pragma unroll
    for (int k = 0; k < 4; k++) {
        int i = k * 256 + tid;
        if (i < PP * 16) {
            int p = i >> 4, c8 = (i & 15) << 3;
            *(uint4*)&tf[p * CS + c8] = tr[k];
        }
    }
    for (int i = tid; i < 15 * CS; i += 256)
        tf[49 * CS + i] = __float2bfloat16(0.f);
    __syncthreads();

    // MMA on all 8 warps: m2 = M half, nw = 16-col quarter
    int m2 = w >> 2, nw = w & 3;
    float acc[2][2][4] = {};
#pragma unroll
    for (int ks = 0; ks < 8; ks++) {
        uint32_t b[2][2];
        {
            uint32_t rr[4];
            uint32_t addr = smem_u32(&tf[((nw << 4) + ((lane >> 4) << 3) + (lane & 7)) * CS
                                         + (ks << 4) + (((lane >> 3) & 1) << 3)]);
            ldsm4(rr, addr);
            b[0][0] = rr[0]; b[0][1] = rr[1]; b[1][0] = rr[2]; b[1][1] = rr[3];
        }
#pragma unroll
        for (int f = 0; f < 2; f++) {
            int fa = (m2 << 1) + f;
            uint32_t a[4];
            ldsm4(a, smem_u32(&cf[((fa << 4) + (lane & 15)) * CS + (ks << 4) + ((lane >> 4) << 3)]));
            mma_bf16(acc[f][0], a, b[0]);
            mma_bf16(acc[f][1], a, b[1]);
        }
    }

    __nv_bfloat16* cv = g_cv + ((size_t)((l * TT + t) * NQ + n)) * CV_K;
#pragma unroll
    for (int f = 0; f < 2; f++) {
        int m0 = ((m2 << 1) + f << 4) + (lane >> 2);
#pragma unroll
        for (int g = 0; g < 2; g++) {
            int nn = (nw << 4) + (g << 3) + ((lane & 3) << 1);
            if (nn < PP) {
                if (m0 < PP) cv[m0 * PP + nn] = __float2bfloat16(acc[f][g][0]);
                if (m0 + 8 < PP) cv[(m0 + 8) * PP + nn] = __float2bfloat16(acc[f][g][2]);
                if (nn + 1 < PP) {
                    if (m0 < PP) cv[m0 * PP + nn + 1] = __float2bfloat16(acc[f][g][1]);
                    if (m0 + 8 < PP) cv[(m0 + 8) * PP + nn + 1] = __float2bfloat16(acc[f][g][3]);
                }
            }
        }
    }
}

// ---------------------------------------------------------------------------
// bf16 mma.sync GEMM (R9 128x128 version, LDG->compute->STS pipeline).
// ---------------------------------------------------------------------------
#define GST 40

__global__ __launch_bounds__(256) void k_gemm_bf(const __nv_bfloat16* __restrict__ A,
                                                 const __nv_bfloat16* __restrict__ Bt,
                                                 const float* __restrict__ bias,
                                                 void* __restrict__ Cv,
                                                 int M, int N, int K, int act, int outbf) {
    __shared__ __nv_bfloat16 As[2][128 * GST];
    __shared__ __nv_bfloat16 Bs[2][128 * GST];
    int tid = threadIdx.x, lane = tid & 31, warp = tid >> 5;
    int wm = (warp & 1) << 6, wn = (warp >> 1) << 5;
    int row0 = blockIdx.y << 7, col0 = blockIdx.x << 7;
    const __nv_bfloat16* Ag = A  + (size_t)row0 * K;
    const __nv_bfloat16* Bg = Bt + (size_t)col0 * K;

    int r1 = tid >> 2, c1 = (tid & 3) << 3;
    int r2 = (tid + 256) >> 2, c2 = ((tid + 256) & 3) << 3;

    *(uint4*)(As[0] + r1 * GST + c1) = *(const uint4*)(Ag + (size_t)r1 * K + c1);
    *(uint4*)(As[0] + r2 * GST + c2) = *(const uint4*)(Ag + (size_t)r2 * K + c2);
    *(uint4*)(Bs[0] + r1 * GST + c1) = *(const uint4*)(Bg + (size_t)r1 * K + c1);
    *(uint4*)(Bs[0] + r2 * GST + c2) = *(const uint4*)(Bg + (size_t)r2 * K + c2);
    __syncthreads();

    float acc[4][4][4] = {};
    int nk = K >> 5;
    for (int i = 0; i < nk; i++) {
        int s = i & 1;
        uint4 ra0, ra1, rb0, rb1;
        bool pre = (i + 1 < nk);
        if (pre) {
            int k0 = (i + 1) << 5;
            ra0 = *(const uint4*)(Ag + (size_t)r1 * K + k0 + c1);
            ra1 = *(const uint4*)(Ag + (size_t)r2 * K + k0 + c2);
            rb0 = *(const uint4*)(Bg + (size_t)r1 * K + k0 + c1);
            rb1 = *(const uint4*)(Bg + (size_t)r2 * K + k0 + c2);
        }
#pragma unroll
        for (int ks = 0; ks < 2; ks++) {
            uint32_t b[4][2];
#pragma unroll
            for (int g = 0; g < 2; g++) {
                uint32_t rr[4];
                uint32_t addr = smem_u32(Bs[s] + (wn + (g << 4) + ((lane >> 4) << 3) + (lane & 7)) * GST
                                         + (ks << 4) + (((lane >> 3) & 1) << 3));
                ldsm4(rr, addr);
                b[g * 2][0] = rr[0]; b[g * 2][1] = rr[1];
                b[g * 2 + 1][0] = rr[2]; b[g * 2 + 1][1] = rr[3];
            }
#pragma unroll
            for (int f = 0; f < 4; f++) {
                uint32_t a[4];
                ldsm4(a, smem_u32(As[s] + (wm + (f << 4) + (lane & 15)) * GST
                                  + (ks << 4) + ((lane >> 4) << 3)));
#pragma unroll
                for (int g = 0; g < 4; g++) mma_bf16(acc[f][g], a, b[g]);
            }
        }
        if (pre) {
            int s2 = s ^ 1;
            *(uint4*)(As[s2] + r1 * GST + c1) = ra0;
            *(uint4*)(As[s2] + r2 * GST + c2) = ra1;
            *(uint4*)(Bs[s2] + r1 * GST + c1) = rb0;
            *(uint4*)(Bs[s2] + r2 * GST + c2) = rb1;
        }
        __syncthreads();
    }
#pragma unroll
    for (int f = 0; f < 4; f++) {
        int m = row0 + wm + (f << 4) + (lane >> 2);
#pragma unroll
        for (int g = 0; g < 4; g++) {
            int nn = col0 + wn + (g << 3) + ((lane & 3) << 1);
            float b0 = bias[nn], b1 = bias[nn + 1];
            float v0 = acc[f][g][0] + b0, v1 = acc[f][g][1] + b1;
            float v2 = acc[f][g][2] + b0, v3 = acc[f][g][3] + b1;
            if (act) { v0 = geluf(v0); v1 = geluf(v1); v2 = geluf(v2); v3 = geluf(v3); }
            if (outbf) {
                __nv_bfloat16* C = (__nv_bfloat16*)Cv;
                C[(size_t)m * N + nn] = __float2bfloat16(v0);
                C[(size_t)m * N + nn + 1] = __float2bfloat16(v1);
                C[(size_t)(m + 8) * N + nn] = __float2bfloat16(v2);
                C[(size_t)(m + 8) * N + nn + 1] = __float2bfloat16(v3);
            } else {
                float* C = (float*)Cv;
                C[(size_t)m * N + nn] = v0;
                C[(size_t)m * N + nn + 1] = v1;
                C[(size_t)(m + 8) * N + nn] = v2;
                C[(size_t)(m + 8) * N + nn + 1] = v3;
            }
        }
    }
}

// ---------------------------------------------------------------------------
// Assemble update-MLP input (bf16)
// ---------------------------------------------------------------------------
__global__ __launch_bounds__(128) void k_assemble() {
    int row = blockIdx.x;
    int n = row >> 4, t = row & 15;
    int tid = threadIdx.x;
    __shared__ float x4[4];
    if (tid == 0) {
        float cx = g_coords[(t * NQ + n) * 2 + 0];
        float cy = g_coords[(t * NQ + n) * 2 + 1];
        float rfx = 0.f, rfy = 0.f, rbx = 0.f, rby = 0.f;
        if (t < TT - 1) {
            rfx = (cx - g_coords[((t + 1) * NQ + n) * 2 + 0]) * (1.f / 128.f);
            rfy = (cy - g_coords[((t + 1) * NQ + n) * 2 + 1]) * (1.f / 96.f);
        }
        if (t > 0) {
            rbx = (cx - g_coords[((t - 1) * NQ + n) * 2 + 0]) * (1.f / 128.f);
            rby = (cy - g_coords[((t - 1) * NQ + n) * 2 + 1]) * (1.f / 96.f);
        }
        x4[0] = rfx; x4[1] = rfy; x4[2] = rbx; x4[3] = rby;
    }
    __syncthreads();
    __nv_bfloat16* dst = g_x + (size_t)row * X_K;
    for (int d = tid; d < D_IN; d += 128) {
        float v;
        if (d == 0) v = g_vis[t * NQ + n];
        else if (d == 1) v = g_conf[t * NQ + n];
        else if (d < 2 + 4 * EMB) {
            int qd = d - 2;
            int l = qd >> 8, k = qd & 255;
            v = g_e[(((size_t)(l * TT + t) * NQ + n) << 8) + k];
        } else {
            int j = d - (2 + 4 * EMB);
            if (j < 4) v = x4[j];
            else if (j < 44) {
                int s = (j - 4) >> 2, dd = (j - 4) & 3;
                v = sinf(x4[dd] * exp2f((float)s));
            } else {
                int s = (j - 44) >> 2, dd = (j - 44) & 3;
                v = cosf(x4[dd] * exp2f((float)s));
            }
        }
        dst[d] = __float2bfloat16(v + g_te[t * D_IN + d]);
    }
}

// ---------------------------------------------------------------------------
// Final tiny GEMV (384->4) + state update
// ---------------------------------------------------------------------------
__global__ __launch_bounds__(128) void k_update(const float* __restrict__ w2,
                                                const float* __restrict__ b2) {
    int row = blockIdx.x;
    int tid = threadIdx.x;
    const float* hrow = g_h2 + (size_t)row * HID;
    float a0 = 0.f, a1 = 0.f, a2 = 0.f, a3 = 0.f;
    for (int i = tid; i < HID; i += 128) {
        float h = hrow[i];
        const float* w = w2 + i * 4;
        a0 = fmaf(h, w[0], a0); a1 = fmaf(h, w[1], a1);
        a2 = fmaf(h, w[2], a2); a3 = fmaf(h, w[3], a3);
    }
#pragma unroll
    for (int o = 16; o; o >>= 1) {
        a0 += __shfl_xor_sync(0xffffffffu, a0, o);
        a1 += __shfl_xor_sync(0xffffffffu, a1, o);
        a2 += __shfl_xor_sync(0xffffffffu, a2, o);
        a3 += __shfl_xor_sync(0xffffffffu, a3, o);
    }
    __shared__ float red[4][4];
    int warp = tid >> 5, lane = tid & 31;
    if (lane == 0) { red[warp][0] = a0; red[warp][1] = a1; red[warp][2] = a2; red[warp][3] = a3; }
    __syncthreads();
    if (tid == 0) {
        float d0 = red[0][0] + red[1][0] + red[2][0] + red[3][0] + b2[0];
        float d1 = red[0][1] + red[1][1] + red[2][1] + red[3][1] + b2[1];
        float d2 = red[0][2] + red[1][2] + red[2][2] + red[3][2] + b2[2];
        float d3 = red[0][3] + red[1][3] + red[2][3] + red[3][3] + b2[3];
        int n = row >> 4, t = row & 15;
        g_coords[(t * NQ + n) * 2 + 0] += d0;
        g_coords[(t * NQ + n) * 2 + 1] += d1;
        g_vis[t * NQ + n]  += d2;
        g_conf[t * NQ + n] += d3;
    }
}

// ---------------------------------------------------------------------------
// Outputs
// ---------------------------------------------------------------------------
__global__ void k_output(float* __restrict__ out) {
    int i = blockIdx.x * blockDim.x + threadIdx.x;
    if (i >= 8192) return;
    if (i < 4096) out[i] = g_coords[i] * 4.f;
    else if (i < 6144) out[i] = 1.f / (1.f + expf(-g_vis[i - 4096]));
    else out[i] = 1.f / (1.f + expf(-g_conf[i - 6144]));
}

// ---------------------------------------------------------------------------
// Launch. Order: conv(1) pools(2) template(3) corr(4, profiled) prep(5) ...
// ---------------------------------------------------------------------------
extern "C" void kernel_launch(void* const* d_in, const int* in_sizes, int n_in,
                              void* d_out, int out_size) {
    const float* video   = (const float*)d_in[0];
    const float* queries = (const float*)d_in[1];
    const float* fnet_w  = (const float*)d_in[2];
    const float* fnet_b  = (const float*)d_in[3];
    const float* fc1_w   = (const float*)d_in[4];
    const float* fc1_b   = (const float*)d_in[5];
    const float* fc2_w   = (const float*)d_in[6];
    const float* fc2_b   = (const float*)d_in[7];
    const float* up_w1   = (const float*)d_in[8];
    const float* up_b1   = (const float*)d_in[9];
    const float* up_w2   = (const float*)d_in[10];
    const float* up_b2   = (const float*)d_in[11];
    const float* time_emb= (const float*)d_in[12];
    float* out = (float*)d_out;

    cudaFuncSetAttribute(k_corr_mma, cudaFuncAttributeMaxDynamicSharedMemorySize, CORR_DSM);

    __nv_bfloat16 *p_cv, *p_h1, *p_x, *p_w1t, *p_w2t, *p_u1t;
    float *p_e, *p_h2;
    cudaGetSymbolAddress((void**)&p_cv,  g_cv);
    cudaGetSymbolAddress((void**)&p_h1,  g_h1);
    cudaGetSymbolAddress((void**)&p_e,   g_e);
    cudaGetSymbolAddress((void**)&p_x,   g_x);
    cudaGetSymbolAddress((void**)&p_h2,  g_h2);
    cudaGetSymbolAddress((void**)&p_w1t, g_w1t);
    cudaGetSymbolAddress((void**)&p_w2t, g_w2t);
    cudaGetSymbolAddress((void**)&p_u1t, g_u1t);

    const int M1 = 4 * TT * NQ;   // 8192
    const int M3 = NQ * TT;       // 2048

    k_conv<<<TT * 96 * 128 / 32, 256>>>(video, fnet_w, fnet_b, queries);  // 1
    k_pools<<<TT * 12 * 16, 256>>>();                                     // 2
    k_template<<<dim3(NQ, 4), 128>>>(queries);                            // 3

    for (int it = 0; it < 4; it++) {
        k_corr_mma<<<dim3(NQ, TT, 4), 256, CORR_DSM>>>();                 // 4 on it=0
        if (it == 0)
            k_prep<<<(PR_ALL + 255) / 256, 256>>>(fc1_w, fc2_w, up_w1, time_emb);
        k_gemm_bf<<<dim3(HID / 128, M1 / 128), 256>>>(p_cv, p_w1t, fc1_b, p_h1, M1, HID, CV_K, 1, 1);
        k_gemm_bf<<<dim3(EMB / 128, M1 / 128), 256>>>(p_h1, p_w2t, fc2_b, p_e, M1, EMB, HID, 0, 0);
        k_assemble<<<M3, 128>>>();
        k_gemm_bf<<<dim3(HID / 128, M3 / 128), 256>>>(p_x, p_u1t, up_b1, p_h2, M3, HID, X_K, 1, 0);
        k_update<<<M3, 128>>>(up_w2, up_b2);
    }
    k_output<<<(8192 + 255) / 256, 256>>>(out);
}

// round 12
// speedup vs baseline: 1.0775x; 1.0347x over previous
#include <cuda_runtime.h>
#include <cuda_bf16.h>
#include <math.h>
#include <stdint.h>

#define TT 16
#define NQ 128
#define LATC 128
#define RR 7
#define PP 49
#define CV_K 2432      // 2401 padded to mult of 32
#define X_K 1152       // 1110 padded
#define HID 384
#define EMB 256
#define D_IN 1110

// ---------------------------------------------------------------------------
// Static device scratch
// ---------------------------------------------------------------------------
__device__ float g_pyr0[TT*96*128*LATC];
__device__ float g_pyr1[TT*48*64*LATC];
__device__ float g_pyr2[TT*24*32*LATC];
__device__ float g_pyr3[TT*12*16*LATC];
__device__ __nv_bfloat16 g_tf[(size_t)4*NQ*PP*LATC];
__device__ __nv_bfloat16 g_cv[(size_t)4*TT*NQ*CV_K];
__device__ __nv_bfloat16 g_h1[(size_t)4*TT*NQ*HID];
__device__ float         g_e [(size_t)4*TT*NQ*EMB];
__device__ __nv_bfloat16 g_x [(size_t)NQ*TT*X_K];
__device__ float         g_h2[(size_t)NQ*TT*HID];
__device__ __nv_bfloat16 g_w1t[(size_t)HID*CV_K];
__device__ __nv_bfloat16 g_w2t[(size_t)EMB*HID];
__device__ __nv_bfloat16 g_u1t[(size_t)HID*X_K];
__device__ float g_te[TT*D_IN];
__device__ float g_coords[TT*NQ*2];
__device__ float g_vis [TT*NQ];
__device__ float g_conf[TT*NQ];

__device__ __forceinline__ float geluf(float x) {
    return 0.5f * x * (1.f + erff(x * 0.70710678118654752440f));
}

__device__ __forceinline__ const float* level_ptr(int l, int& Hl, int& Wl) {
    switch (l) {
        case 0: Hl = 96; Wl = 128; return g_pyr0;
        case 1: Hl = 48; Wl = 64;  return g_pyr1;
        case 2: Hl = 24; Wl = 32;  return g_pyr2;
        default:Hl = 12; Wl = 16;  return g_pyr3;
    }
}

// ---------------------------------------------------------------------------
// mma.sync / ldmatrix helpers (baseline PTX, sm_103-safe)
// ---------------------------------------------------------------------------
__device__ __forceinline__ uint32_t smem_u32(const void* p) {
    uint32_t a;
    asm("{ .reg .u64 t; cvta.to.shared.u64 t, %1; cvt.u32.u64 %0, t; }" : "=r"(a) : "l"(p));
    return a;
}
__device__ __forceinline__ void ldsm4(uint32_t* r, uint32_t a) {
    asm volatile("ldmatrix.sync.aligned.m8n8.x4.shared.b16 {%0,%1,%2,%3}, [%4];"
        : "=r"(r[0]), "=r"(r[1]), "=r"(r[2]), "=r"(r[3]) : "r"(a));
}
__device__ __forceinline__ void mma_bf16(float* d, const uint32_t* a, const uint32_t* b) {
    asm volatile("mma.sync.aligned.m16n8k16.row.col.f32.bf16.bf16.f32 "
        "{%0,%1,%2,%3},{%4,%5,%6,%7},{%8,%9},{%0,%1,%2,%3};"
        : "+f"(d[0]), "+f"(d[1]), "+f"(d[2]), "+f"(d[3])
        : "r"(a[0]), "r"(a[1]), "r"(a[2]), "r"(a[3]), "r"(b[0]), "r"(b[1]));
}

// ---------------------------------------------------------------------------
// 4x4/s4 conv + bias + channel L2 norm. Warp-per-pixel x4, block 0 also inits
// ---------------------------------------------------------------------------
__global__ __launch_bounds__(256) void k_conv(const float* __restrict__ video,
                                              const float* __restrict__ w,
                                              const float* __restrict__ b,
                                              const float* __restrict__ q) {
    __shared__ float wsm[48][LATC];
    __shared__ float bsm[LATC];
    int tid = threadIdx.x, lane = tid & 31, warp = tid >> 5;
    for (int i = tid; i < 48 * LATC; i += 256) {
        int c = i / 48, k = i % 48;
        wsm[k][c] = w[i];
    }
    if (tid < LATC) bsm[tid] = b[tid];
    if (blockIdx.x == 0) {
        for (int i = tid; i < TT * NQ; i += 256) {
            int n = i % NQ;
            g_coords[i * 2 + 0] = q[n * 3 + 1] * 0.25f;
            g_coords[i * 2 + 1] = q[n * 3 + 2] * 0.25f;
            g_vis[i]  = 0.f;
            g_conf[i] = 0.f;
        }
    }
    __syncthreads();

#pragma unroll
    for (int px = 0; px < 4; px++) {
        int pix = blockIdx.x * 32 + warp * 4 + px;
        int x = pix & 127; int r = pix >> 7; int y = r % 96; int tf = r / 96;

        float p0, p1 = 0.f;
        {
            int k = lane;
            int ci = k / 16, kk = k % 16, ky = kk / 4, kx = kk % 4;
            p0 = video[(((size_t)tf * 3 + ci) * 384 + (y * 4 + ky)) * 512 + (x * 4 + kx)];
            p0 = 2.f * (p0 * (1.f / 255.f)) - 1.f;
            if (lane < 16) {
                k = 32 + lane;
                ci = k / 16; kk = k % 16; ky = kk / 4; kx = kk % 4;
                p1 = video[(((size_t)tf * 3 + ci) * 384 + (y * 4 + ky)) * 512 + (x * 4 + kx)];
                p1 = 2.f * (p1 * (1.f / 255.f)) - 1.f;
            }
        }
        float acc[4];
#pragma unroll
        for (int j = 0; j < 4; j++) acc[j] = bsm[lane + 32 * j];
#pragma unroll
        for (int k = 0; k < 32; k++) {
            float v = __shfl_sync(0xffffffffu, p0, k);
#pragma unroll
            for (int j = 0; j < 4; j++) acc[j] = fmaf(v, wsm[k][lane + 32 * j], acc[j]);
        }
#pragma unroll
        for (int k = 0; k < 16; k++) {
            float v = __shfl_sync(0xffffffffu, p1, k);
#pragma unroll
            for (int j = 0; j < 4; j++) acc[j] = fmaf(v, wsm[32 + k][lane + 32 * j], acc[j]);
        }
        float s = acc[0] * acc[0] + acc[1] * acc[1] + acc[2] * acc[2] + acc[3] * acc[3];
#pragma unroll
        for (int o = 16; o; o >>= 1) s += __shfl_xor_sync(0xffffffffu, s, o);
        float inv = rsqrtf(fmaxf(s, 1e-12f));
        float* dst = g_pyr0 + (size_t)pix * LATC;
#pragma unroll
        for (int j = 0; j < 4; j++) dst[lane + 32 * j] = acc[j] * inv;
    }
}

// ---------------------------------------------------------------------------
// Hierarchical pools: one block = 8x8 pyr0 patch x 128ch -> l1,l2,l3 cascaded
// ---------------------------------------------------------------------------
__global__ __launch_bounds__(256) void k_pools() {
    __shared__ float sp[8 * 8 * 128];
    __shared__ float s1[4 * 4 * 128];
    __shared__ float s2[2 * 2 * 128];
    int tid = threadIdx.x;
    int bid = blockIdx.x;
    int gx = bid & 15; int r = bid >> 4; int gy = r % 12; int t = r / 12;
    int y0 = gy * 8, x0 = gx * 8;

#pragma unroll
    for (int k = 0; k < 8; k++) {
        int f4 = k * 256 + tid;
        int e = f4 << 2;
        int c = e & 127, dyx = e >> 7;
        int dy = dyx >> 3, dx = dyx & 7;
        *(float4*)&sp[e] = *(const float4*)(g_pyr0 +
            (((size_t)t * 96 + y0 + dy) * 128 + (x0 + dx)) * LATC + c);
    }
    __syncthreads();
#pragma unroll
    for (int k = 0; k < 8; k++) {
        int u = k * 256 + tid;
        int c = u & 127, pix = u >> 7;
        int ly = pix >> 2, lx = pix & 3;
        float v = 0.25f * (sp[((2*ly)*8 + 2*lx)*128 + c] + sp[((2*ly)*8 + 2*lx+1)*128 + c]
                         + sp[((2*ly+1)*8 + 2*lx)*128 + c] + sp[((2*ly+1)*8 + 2*lx+1)*128 + c]);
        s1[u] = v;
        g_pyr1[(((size_t)t * 48 + gy*4 + ly) * 64 + gx*4 + lx) * LATC + c] = v;
    }
    __syncthreads();
#pragma unroll
    for (int k = 0; k < 2; k++) {
        int u = k * 256 + tid;
        int c = u & 127, pix = u >> 7;
        int ly = pix >> 1, lx = pix & 1;
        float v = 0.25f * (s1[((2*ly)*4 + 2*lx)*128 + c] + s1[((2*ly)*4 + 2*lx+1)*128 + c]
                         + s1[((2*ly+1)*4 + 2*lx)*128 + c] + s1[((2*ly+1)*4 + 2*lx+1)*128 + c]);
        s2[u] = v;
        g_pyr2[(((size_t)t * 24 + gy*2 + ly) * 32 + gx*2 + lx) * LATC + c] = v;
    }
    __syncthreads();
    if (tid < 128) {
        float v = 0.25f * (s2[tid] + s2[128 + tid] + s2[256 + tid] + s2[384 + tid]);
        g_pyr3[(((size_t)t * 12 + gy) * 16 + gx) * LATC + tid] = v;
    }
}

// ---------------------------------------------------------------------------
// Template features -> bf16 [l][n][p][c]
// ---------------------------------------------------------------------------
__global__ __launch_bounds__(128) void k_template(const float* __restrict__ q) {
    int n = blockIdx.x, l = blockIdx.y, c = threadIdx.x;
    int Hl, Wl;
    const float* fm = level_ptr(l, Hl, Wl);
    float qf = q[n * 3 + 0];
    float inv = exp2f(-(float)l) * 0.25f;
    float cx = q[n * 3 + 1] * inv, cy = q[n * 3 + 2] * inv;
    float tpos = fminf(fmaxf(qf, 0.f), (float)(TT - 1));
    int t0 = (int)floorf(tpos);
    float wt = tpos - (float)t0;
    int t1 = min(t0 + 1, TT - 1);
    const float* f0 = fm + (size_t)t0 * Hl * Wl * LATC;
    const float* f1 = fm + (size_t)t1 * Hl * Wl * LATC;
    __nv_bfloat16* dst = g_tf + (((size_t)l * NQ + n) * PP) * LATC + c;
    for (int p = 0; p < PP; p++) {
        int h = p / RR, ww = p % RR;
        float px = fminf(fmaxf(cx + (float)(h - 3), 0.f), (float)Wl - 1.f);
        float py = fminf(fmaxf(cy + (float)(ww - 3), 0.f), (float)Hl - 1.f);
        int x0 = (int)floorf(px); float wx = px - (float)x0; int x1 = min(x0 + 1, Wl - 1);
        int y0 = (int)floorf(py); float wy = py - (float)y0; int y1 = min(y0 + 1, Hl - 1);
        int o00 = (y0 * Wl + x0) * LATC + c, o01 = (y0 * Wl + x1) * LATC + c;
        int o10 = (y1 * Wl + x0) * LATC + c, o11 = (y1 * Wl + x1) * LATC + c;
        float v = (1.f - wy) * ((1.f - wx) * f0[o00] + wx * f0[o01])
                +        wy  * ((1.f - wx) * f0[o10] + wx * f0[o11]);
        if (wt > 0.f) {
            float v1 = (1.f - wy) * ((1.f - wx) * f1[o00] + wx * f1[o01])
                     +        wy  * ((1.f - wx) * f1[o10] + wx * f1[o11]);
            v = v * (1.f - wt) + v1 * wt;
        }
        dst[p * LATC] = __float2bfloat16(v);
    }
}

// ---------------------------------------------------------------------------
// Merged prep: 3 weight transposes + 2 pads + time-embedding interp
// ---------------------------------------------------------------------------
#define PR_W1 (HID * CV_K)
#define PR_W2 (EMB * HID)
#define PR_U1 (HID * X_K)
#define PR_CV ((4 * TT * NQ) * (CV_K - 2401))
#define PR_X  ((NQ * TT) * (X_K - D_IN))
#define PR_TE (TT * D_IN)
#define PR_ALL (PR_W1 + PR_W2 + PR_U1 + PR_CV + PR_X + PR_TE)

__global__ void k_prep(const float* __restrict__ fc1_w,
                       const float* __restrict__ fc2_w,
                       const float* __restrict__ up_w1,
                       const float* __restrict__ emb) {
    int i = blockIdx.x * blockDim.x + threadIdx.x;
    if (i < PR_W1) {
        int n = i / CV_K, k = i - n * CV_K;
        g_w1t[i] = __float2bfloat16((k < 2401) ? fc1_w[(size_t)k * HID + n] : 0.f);
        return;
    }
    i -= PR_W1;
    if (i < PR_W2) {
        int n = i / HID, k = i - n * HID;
        g_w2t[i] = __float2bfloat16(fc2_w[(size_t)k * EMB + n]);
        return;
    }
    i -= PR_W2;
    if (i < PR_U1) {
        int n = i / X_K, k = i - n * X_K;
        g_u1t[i] = __float2bfloat16((k < D_IN) ? up_w1[(size_t)k * HID + n] : 0.f);
        return;
    }
    i -= PR_U1;
    if (i < PR_CV) {
        int cw = CV_K - 2401;
        int r = i / cw, c = i - r * cw;
        g_cv[(size_t)r * CV_K + 2401 + c] = __float2bfloat16(0.f);
        return;
    }
    i -= PR_CV;
    if (i < PR_X) {
        int cw = X_K - D_IN;
        int r = i / cw, c = i - r * cw;
        g_x[(size_t)r * X_K + D_IN + c] = __float2bfloat16(0.f);
        return;
    }
    i -= PR_X;
    if (i < PR_TE) {
        int t = i / D_IN, d = i % D_IN;
        float j = ((float)t + 0.5f) * (50.f / 16.f) - 0.5f;
        j = fminf(fmaxf(j, 0.f), 49.f);
        int j0 = (int)floorf(j);
        int j1 = min(j0 + 1, 49);
        float w = j - (float)j0;
        g_te[i] = emb[j0 * D_IN + d] * (1.f - w) + emb[j1 * D_IN + d] * w;
    }
}

// ---------------------------------------------------------------------------
// Fused bilinear sample + 49x49x128 correlation via mma.sync (R9 version).
// ---------------------------------------------------------------------------
#define CS 136

__global__ __launch_bounds__(256) void k_corr_mma() {
    __shared__ __nv_bfloat16 cf[64 * CS];
    __shared__ __nv_bfloat16 tf[64 * CS];
    __shared__ int   sO[PP][4];
    __shared__ float sW[PP][2];
    int n = blockIdx.x, t = blockIdx.y, l = blockIdx.z;
    int tid = threadIdx.x, lane = tid & 31, w = tid >> 5;
    int Hl, Wl;
    const float* fm = level_ptr(l, Hl, Wl);
    fm += (size_t)t * Hl * Wl * LATC;

    if (tid < PP) {
        float inv = exp2f(-(float)l);
        float cx = g_coords[(t * NQ + n) * 2 + 0] * inv;
        float cy = g_coords[(t * NQ + n) * 2 + 1] * inv;
        int h = tid / RR, ww = tid % RR;
        float px = fminf(fmaxf(cx + (float)(h - 3), 0.f), (float)Wl - 1.f);
        float py = fminf(fmaxf(cy + (float)(ww - 3), 0.f), (float)Hl - 1.f);
        int x0 = (int)floorf(px); float wx = px - (float)x0; int x1 = min(x0 + 1, Wl - 1);
        int y0 = (int)floorf(py); float wy = py - (float)y0; int y1 = min(y0 + 1, Hl - 1);
        sO[tid][0] = (y0 * Wl + x0) * LATC;
        sO[tid][1] = (y0 * Wl + x1) * LATC;
        sO[tid][2] = (y1 * Wl + x0) * LATC;
        sO[tid][3] = (y1 * Wl + x1) * LATC;
        sW[tid][0] = wx; sW[tid][1] = wy;
    }
    for (int i = tid; i < 15 * CS; i += 256) {
        cf[49 * CS + i] = __float2bfloat16(0.f);
        tf[49 * CS + i] = __float2bfloat16(0.f);
    }
    const __nv_bfloat16* tfg = g_tf + (((size_t)l * NQ + n) * PP) * LATC;
    for (int i = tid; i < PP * 16; i += 256) {
        int p = i >> 4, c8 = (i & 15) << 3;
        *(uint4*)&tf[p * CS + c8] = *(const uint4*)(tfg + p * LATC + c8);
    }
    __syncthreads();
    for (int i = tid; i < PP * 32; i += 256) {
        int p = i >> 5, c4 = (i & 31) << 2;
        float wx = sW[p][0], wy = sW[p][1];
        float w00 = (1.f - wy) * (1.f - wx), w01 = (1.f - wy) * wx;
        float w10 = wy * (1.f - wx),         w11 = wy * wx;
        float4 v00 = *(const float4*)(fm + sO[p][0] + c4);
        float4 v01 = *(const float4*)(fm + sO[p][1] + c4);
        float4 v10 = *(const float4*)(fm + sO[p][2] + c4);
        float4 v11 = *(const float4*)(fm + sO[p][3] + c4);
        float r0 = w00 * v00.x + w01 * v01.x + w10 * v10.x + w11 * v11.x;
        float r1 = w00 * v00.y + w01 * v01.y + w10 * v10.y + w11 * v11.y;
        float r2 = w00 * v00.z + w01 * v01.z + w10 * v10.z + w11 * v11.z;
        float r3 = w00 * v00.w + w01 * v01.w + w10 * v10.w + w11 * v11.w;
        __nv_bfloat162* dst = (__nv_bfloat162*)&cf[p * CS + c4];
        dst[0] = __floats2bfloat162_rn(r0, r1);
        dst[1] = __floats2bfloat162_rn(r2, r3);
    }
    __syncthreads();

    int m2 = w >> 2, nw = w & 3;
    float acc[2][2][4] = {};
#pragma unroll
    for (int ks = 0; ks < 8; ks++) {
        uint32_t b[2][2];
        {
            uint32_t rr[4];
            uint32_t addr = smem_u32(&tf[((nw << 4) + ((lane >> 4) << 3) + (lane & 7)) * CS
                                         + (ks << 4) + (((lane >> 3) & 1) << 3)]);
            ldsm4(rr, addr);
            b[0][0] = rr[0]; b[0][1] = rr[1]; b[1][0] = rr[2]; b[1][1] = rr[3];
        }
#pragma unroll
        for (int f = 0; f < 2; f++) {
            int fa = (m2 << 1) + f;
            uint32_t a[4];
            ldsm4(a, smem_u32(&cf[((fa << 4) + (lane & 15)) * CS + (ks << 4) + ((lane >> 4) << 3)]));
            mma_bf16(acc[f][0], a, b[0]);
            mma_bf16(acc[f][1], a, b[1]);
        }
    }

    __nv_bfloat16* cv = g_cv + ((size_t)((l * TT + t) * NQ + n)) * CV_K;
#pragma unroll
    for (int f = 0; f < 2; f++) {
        int m0 = ((m2 << 1) + f << 4) + (lane >> 2);
#pragma unroll
        for (int g = 0; g < 2; g++) {
            int nn = (nw << 4) + (g << 3) + ((lane & 3) << 1);
            if (nn < PP) {
                if (m0 < PP) cv[m0 * PP + nn] = __float2bfloat16(acc[f][g][0]);
                if (m0 + 8 < PP) cv[(m0 + 8) * PP + nn] = __float2bfloat16(acc[f][g][2]);
                if (nn + 1 < PP) {
                    if (m0 < PP) cv[m0 * PP + nn + 1] = __float2bfloat16(acc[f][g][1]);
                    if (m0 + 8 < PP) cv[(m0 + 8) * PP + nn + 1] = __float2bfloat16(acc[f][g][3]);
                }
            }
        }
    }
}

// ---------------------------------------------------------------------------
// bf16 mma.sync GEMM, 128x128 CTA tile (R9), LDG->compute->STS pipeline.
// ---------------------------------------------------------------------------
#define GST 40

__global__ __launch_bounds__(256) void k_gemm_bf(const __nv_bfloat16* __restrict__ A,
                                                 const __nv_bfloat16* __restrict__ Bt,
                                                 const float* __restrict__ bias,
                                                 void* __restrict__ Cv,
                                                 int M, int N, int K, int act, int outbf) {
    __shared__ __nv_bfloat16 As[2][128 * GST];
    __shared__ __nv_bfloat16 Bs[2][128 * GST];
    int tid = threadIdx.x, lane = tid & 31, warp = tid >> 5;
    int wm = (warp & 1) << 6, wn = (warp >> 1) << 5;
    int row0 = blockIdx.y << 7, col0 = blockIdx.x << 7;
    const __nv_bfloat16* Ag = A  + (size_t)row0 * K;
    const __nv_bfloat16* Bg = Bt + (size_t)col0 * K;

    int r1 = tid >> 2, c1 = (tid & 3) << 3;
    int r2 = (tid + 256) >> 2, c2 = ((tid + 256) & 3) << 3;

    *(uint4*)(As[0] + r1 * GST + c1) = *(const uint4*)(Ag + (size_t)r1 * K + c1);
    *(uint4*)(As[0] + r2 * GST + c2) = *(const uint4*)(Ag + (size_t)r2 * K + c2);
    *(uint4*)(Bs[0] + r1 * GST + c1) = *(const uint4*)(Bg + (size_t)r1 * K + c1);
    *(uint4*)(Bs[0] + r2 * GST + c2) = *(const uint4*)(Bg + (size_t)r2 * K + c2);
    __syncthreads();

    float acc[4][4][4] = {};
    int nk = K >> 5;
    for (int i = 0; i < nk; i++) {
        int s = i & 1;
        uint4 ra0, ra1, rb0, rb1;
        bool pre = (i + 1 < nk);
        if (pre) {
            int k0 = (i + 1) << 5;
            ra0 = *(const uint4*)(Ag + (size_t)r1 * K + k0 + c1);
            ra1 = *(const uint4*)(Ag + (size_t)r2 * K + k0 + c2);
            rb0 = *(const uint4*)(Bg + (size_t)r1 * K + k0 + c1);
            rb1 = *(const uint4*)(Bg + (size_t)r2 * K + k0 + c2);
        }
#pragma unroll
        for (int ks = 0; ks < 2; ks++) {
            uint32_t b[4][2];
#pragma unroll
            for (int g = 0; g < 2; g++) {
                uint32_t rr[4];
                uint32_t addr = smem_u32(Bs[s] + (wn + (g << 4) + ((lane >> 4) << 3) + (lane & 7)) * GST
                                         + (ks << 4) + (((lane >> 3) & 1) << 3));
                ldsm4(rr, addr);
                b[g * 2][0] = rr[0]; b[g * 2][1] = rr[1];
                b[g * 2 + 1][0] = rr[2]; b[g * 2 + 1][1] = rr[3];
            }
#pragma unroll
            for (int f = 0; f < 4; f++) {
                uint32_t a[4];
                ldsm4(a, smem_u32(As[s] + (wm + (f << 4) + (lane & 15)) * GST
                                  + (ks << 4) + ((lane >> 4) << 3)));
#pragma unroll
                for (int g = 0; g < 4; g++) mma_bf16(acc[f][g], a, b[g]);
            }
        }
        if (pre) {
            int s2 = s ^ 1;
            *(uint4*)(As[s2] + r1 * GST + c1) = ra0;
            *(uint4*)(As[s2] + r2 * GST + c2) = ra1;
            *(uint4*)(Bs[s2] + r1 * GST + c1) = rb0;
            *(uint4*)(Bs[s2] + r2 * GST + c2) = rb1;
        }
        __syncthreads();
    }
#pragma unroll
    for (int f = 0; f < 4; f++) {
        int m = row0 + wm + (f << 4) + (lane >> 2);
#pragma unroll
        for (int g = 0; g < 4; g++) {
            int nn = col0 + wn + (g << 3) + ((lane & 3) << 1);
            float b0 = bias[nn], b1 = bias[nn + 1];
            float v0 = acc[f][g][0] + b0, v1 = acc[f][g][1] + b1;
            float v2 = acc[f][g][2] + b0, v3 = acc[f][g][3] + b1;
            if (act) { v0 = geluf(v0); v1 = geluf(v1); v2 = geluf(v2); v3 = geluf(v3); }
            if (outbf) {
                __nv_bfloat16* C = (__nv_bfloat16*)Cv;
                C[(size_t)m * N + nn] = __float2bfloat16(v0);
                C[(size_t)m * N + nn + 1] = __float2bfloat16(v1);
                C[(size_t)(m + 8) * N + nn] = __float2bfloat16(v2);
                C[(size_t)(m + 8) * N + nn + 1] = __float2bfloat16(v3);
            } else {
                float* C = (float*)Cv;
                C[(size_t)m * N + nn] = v0;
                C[(size_t)m * N + nn + 1] = v1;
                C[(size_t)(m + 8) * N + nn] = v2;
                C[(size_t)(m + 8) * N + nn + 1] = v3;
            }
        }
    }
}

// ---------------------------------------------------------------------------
// bf16 mma.sync GEMM, 64x64 CTA tile (for small-grid shapes: up-GEMM).
// 128 threads, 4 warps (2Mx2N), warp tile 32x32, BK=32.
// ---------------------------------------------------------------------------
__global__ __launch_bounds__(128) void k_gemm64(const __nv_bfloat16* __restrict__ A,
                                                const __nv_bfloat16* __restrict__ Bt,
                                                const float* __restrict__ bias,
                                                void* __restrict__ Cv,
                                                int M, int N, int K, int act, int outbf) {
    __shared__ __nv_bfloat16 As[2][64 * GST];
    __shared__ __nv_bfloat16 Bs[2][64 * GST];
    int tid = threadIdx.x, lane = tid & 31, warp = tid >> 5;
    int wm = (warp & 1) << 5, wn = (warp >> 1) << 5;
    int row0 = blockIdx.y << 6, col0 = blockIdx.x << 6;
    const __nv_bfloat16* Ag = A  + (size_t)row0 * K;
    const __nv_bfloat16* Bg = Bt + (size_t)col0 * K;

    int r1 = tid >> 2, c1 = (tid & 3) << 3;
    int r2 = (tid + 128) >> 2, c2 = ((tid + 128) & 3) << 3;

    *(uint4*)(As[0] + r1 * GST + c1) = *(const uint4*)(Ag + (size_t)r1 * K + c1);
    *(uint4*)(As[0] + r2 * GST + c2) = *(const uint4*)(Ag + (size_t)r2 * K + c2);
    *(uint4*)(Bs[0] + r1 * GST + c1) = *(const uint4*)(Bg + (size_t)r1 * K + c1);
    *(uint4*)(Bs[0] + r2 * GST + c2) = *(const uint4*)(Bg + (size_t)r2 * K + c2);
    __syncthreads();

    float acc[2][4][4] = {};
    int nk = K >> 5;
    for (int i = 0; i < nk; i++) {
        int s = i & 1;
        uint4 ra0, ra1, rb0, rb1;
        bool pre = (i + 1 < nk);
        if (pre) {
            int k0 = (i + 1) << 5;
            ra0 = *(const uint4*)(Ag + (size_t)r1 * K + k0 + c1);
            ra1 = *(const uint4*)(Ag + (size_t)r2 * K + k0 + c2);
            rb0 = *(const uint4*)(Bg + (size_t)r1 * K + k0 + c1);
            rb1 = *(const uint4*)(Bg + (size_t)r2 * K + k0 + c2);
        }
#pragma unroll
        for (int ks = 0; ks < 2; ks++) {
            uint32_t b[4][2];
#pragma unroll
            for (int g = 0; g < 2; g++) {
                uint32_t rr[4];
                uint32_t addr = smem_u32(Bs[s] + (wn + (g << 4) + ((lane >> 4) << 3) + (lane & 7)) * GST
                                         + (ks << 4) + (((lane >> 3) & 1) << 3));
                ldsm4(rr, addr);
                b[g * 2][0] = rr[0]; b[g * 2][1] = rr[1];
                b[g * 2 + 1][0] = rr[2]; b[g * 2 + 1][1] = rr[3];
            }
#pragma unroll
            for (int f = 0; f < 2; f++) {
                uint32_t a[4];
                ldsm4(a, smem_u32(As[s] + (wm + (f << 4) + (lane & 15)) * GST
                                  + (ks << 4) + ((lane >> 4) << 3)));
#pragma unroll
                for (int g = 0; g < 4; g++) mma_bf16(acc[f][g], a, b[g]);
            }
        }
        if (pre) {
            int s2 = s ^ 1;
            *(uint4*)(As[s2] + r1 * GST + c1) = ra0;
            *(uint4*)(As[s2] + r2 * GST + c2) = ra1;
            *(uint4*)(Bs[s2] + r1 * GST + c1) = rb0;
            *(uint4*)(Bs[s2] + r2 * GST + c2) = rb1;
        }
        __syncthreads();
    }
#pragma unroll
    for (int f = 0; f < 2; f++) {
        int m = row0 + wm + (f << 4) + (lane >> 2);
#pragma unroll
        for (int g = 0; g < 4; g++) {
            int nn = col0 + wn + (g << 3) + ((lane & 3) << 1);
            float b0 = bias[nn], b1 = bias[nn + 1];
            float v0 = acc[f][g][0] + b0, v1 = acc[f][g][1] + b1;
            float v2 = acc[f][g][2] + b0, v3 = acc[f][g][3] + b1;
            if (act) { v0 = geluf(v0); v1 = geluf(v1); v2 = geluf(v2); v3 = geluf(v3); }
            if (outbf) {
                __nv_bfloat16* C = (__nv_bfloat16*)Cv;
                C[(size_t)m * N + nn] = __float2bfloat16(v0);
                C[(size_t)m * N + nn + 1] = __float2bfloat16(v1);
                C[(size_t)(m + 8) * N + nn] = __float2bfloat16(v2);
                C[(size_t)(m + 8) * N + nn + 1] = __float2bfloat16(v3);
            } else {
                float* C = (float*)Cv;
                C[(size_t)m * N + nn] = v0;
                C[(size_t)m * N + nn + 1] = v1;
                C[(size_t)(m + 8) * N + nn] = v2;
                C[(size_t)(m + 8) * N + nn + 1] = v3;
            }
        }
    }
}

// ---------------------------------------------------------------------------
// Assemble update-MLP input (bf16)
// ---------------------------------------------------------------------------
__global__ __launch_bounds__(128) void k_assemble() {
    int row = blockIdx.x;
    int n = row >> 4, t = row & 15;
    int tid = threadIdx.x;
    __shared__ float x4[4];
    if (tid == 0) {
        float cx = g_coords[(t * NQ + n) * 2 + 0];
        float cy = g_coords[(t * NQ + n) * 2 + 1];
        float rfx = 0.f, rfy = 0.f, rbx = 0.f, rby = 0.f;
        if (t < TT - 1) {
            rfx = (cx - g_coords[((t + 1) * NQ + n) * 2 + 0]) * (1.f / 128.f);
            rfy = (cy - g_coords[((t + 1) * NQ + n) * 2 + 1]) * (1.f / 96.f);
        }
        if (t > 0) {
            rbx = (cx - g_coords[((t - 1) * NQ + n) * 2 + 0]) * (1.f / 128.f);
            rby = (cy - g_coords[((t - 1) * NQ + n) * 2 + 1]) * (1.f / 96.f);
        }
        x4[0] = rfx; x4[1] = rfy; x4[2] = rbx; x4[3] = rby;
    }
    __syncthreads();
    __nv_bfloat16* dst = g_x + (size_t)row * X_K;
    for (int d = tid; d < D_IN; d += 128) {
        float v;
        if (d == 0) v = g_vis[t * NQ + n];
        else if (d == 1) v = g_conf[t * NQ + n];
        else if (d < 2 + 4 * EMB) {
            int qd = d - 2;
            int l = qd >> 8, k = qd & 255;
            v = g_e[(((size_t)(l * TT + t) * NQ + n) << 8) + k];
        } else {
            int j = d - (2 + 4 * EMB);
            if (j < 4) v = x4[j];
            else if (j < 44) {
                int s = (j - 4) >> 2, dd = (j - 4) & 3;
                v = sinf(x4[dd] * exp2f((float)s));
            } else {
                int s = (j - 44) >> 2, dd = (j - 44) & 3;
                v = cosf(x4[dd] * exp2f((float)s));
            }
        }
        dst[d] = __float2bfloat16(v + g_te[t * D_IN + d]);
    }
}

// ---------------------------------------------------------------------------
// Final tiny GEMV (384->4) + state update
// ---------------------------------------------------------------------------
__global__ __launch_bounds__(128) void k_update(const float* __restrict__ w2,
                                                const float* __restrict__ b2) {
    int row = blockIdx.x;
    int tid = threadIdx.x;
    const float* hrow = g_h2 + (size_t)row * HID;
    float a0 = 0.f, a1 = 0.f, a2 = 0.f, a3 = 0.f;
    for (int i = tid; i < HID; i += 128) {
        float h = hrow[i];
        const float* w = w2 + i * 4;
        a0 = fmaf(h, w[0], a0); a1 = fmaf(h, w[1], a1);
        a2 = fmaf(h, w[2], a2); a3 = fmaf(h, w[3], a3);
    }
#pragma unroll
    for (int o = 16; o; o >>= 1) {
        a0 += __shfl_xor_sync(0xffffffffu, a0, o);
        a1 += __shfl_xor_sync(0xffffffffu, a1, o);
        a2 += __shfl_xor_sync(0xffffffffu, a2, o);
        a3 += __shfl_xor_sync(0xffffffffu, a3, o);
    }
    __shared__ float red[4][4];
    int warp = tid >> 5, lane = tid & 31;
    if (lane == 0) { red[warp][0] = a0; red[warp][1] = a1; red[warp][2] = a2; red[warp][3] = a3; }
    __syncthreads();
    if (tid == 0) {
        float d0 = red[0][0] + red[1][0] + red[2][0] + red[3][0] + b2[0];
        float d1 = red[0][1] + red[1][1] + red[2][1] + red[3][1] + b2[1];
        float d2 = red[0][2] + red[1][2] + red[2][2] + red[3][2] + b2[2];
        float d3 = red[0][3] + red[1][3] + red[2][3] + red[3][3] + b2[3];
        int n = row >> 4, t = row & 15;
        g_coords[(t * NQ + n) * 2 + 0] += d0;
        g_coords[(t * NQ + n) * 2 + 1] += d1;
        g_vis[t * NQ + n]  += d2;
        g_conf[t * NQ + n] += d3;
    }
}

// ---------------------------------------------------------------------------
// Outputs
// ---------------------------------------------------------------------------
__global__ void k_output(float* __restrict__ out) {
    int i = blockIdx.x * blockDim.x + threadIdx.x;
    if (i >= 8192) return;
    if (i < 4096) out[i] = g_coords[i] * 4.f;
    else if (i < 6144) out[i] = 1.f / (1.f + expf(-g_vis[i - 4096]));
    else out[i] = 1.f / (1.f + expf(-g_conf[i - 6144]));
}

// ---------------------------------------------------------------------------
// Launch. Order: conv(1) pools(2) template(3) corr(4, profiled) prep(5) ...
// ---------------------------------------------------------------------------
extern "C" void kernel_launch(void* const* d_in, const int* in_sizes, int n_in,
                              void* d_out, int out_size) {
    const float* video   = (const float*)d_in[0];
    const float* queries = (const float*)d_in[1];
    const float* fnet_w  = (const float*)d_in[2];
    const float* fnet_b  = (const float*)d_in[3];
    const float* fc1_w   = (const float*)d_in[4];
    const float* fc1_b   = (const float*)d_in[5];
    const float* fc2_w   = (const float*)d_in[6];
    const float* fc2_b   = (const float*)d_in[7];
    const float* up_w1   = (const float*)d_in[8];
    const float* up_b1   = (const float*)d_in[9];
    const float* up_w2   = (const float*)d_in[10];
    const float* up_b2   = (const float*)d_in[11];
    const float* time_emb= (const float*)d_in[12];
    float* out = (float*)d_out;

    __nv_bfloat16 *p_cv, *p_h1, *p_x, *p_w1t, *p_w2t, *p_u1t;
    float *p_e, *p_h2;
    cudaGetSymbolAddress((void**)&p_cv,  g_cv);
    cudaGetSymbolAddress((void**)&p_h1,  g_h1);
    cudaGetSymbolAddress((void**)&p_e,   g_e);
    cudaGetSymbolAddress((void**)&p_x,   g_x);
    cudaGetSymbolAddress((void**)&p_h2,  g_h2);
    cudaGetSymbolAddress((void**)&p_w1t, g_w1t);
    cudaGetSymbolAddress((void**)&p_w2t, g_w2t);
    cudaGetSymbolAddress((void**)&p_u1t, g_u1t);

    const int M1 = 4 * TT * NQ;   // 8192
    const int M3 = NQ * TT;       // 2048

    k_conv<<<TT * 96 * 128 / 32, 256>>>(video, fnet_w, fnet_b, queries);  // 1
    k_pools<<<TT * 12 * 16, 256>>>();                                     // 2
    k_template<<<dim3(NQ, 4), 128>>>(queries);                            // 3

    for (int it = 0; it < 4; it++) {
        k_corr_mma<<<dim3(NQ, TT, 4), 256>>>();                           // 4 on it=0
        if (it == 0)
            k_prep<<<(PR_ALL + 255) / 256, 256>>>(fc1_w, fc2_w, up_w1, time_emb);
        k_gemm_bf<<<dim3(HID / 128, M1 / 128), 256>>>(p_cv, p_w1t, fc1_b, p_h1, M1, HID, CV_K, 1, 1);
        k_gemm_bf<<<dim3(EMB / 128, M1 / 128), 256>>>(p_h1, p_w2t, fc2_b, p_e, M1, EMB, HID, 0, 0);
        k_assemble<<<M3, 128>>>();
        k_gemm64<<<dim3(HID / 64, M3 / 64), 128>>>(p_x, p_u1t, up_b1, p_h2, M3, HID, X_K, 1, 0);
        k_update<<<M3, 128>>>(up_w2, up_b2);
    }
    k_output<<<(8192 + 255) / 256, 256>>>(out);
}

// round 15
// speedup vs baseline: 1.1271x; 1.0460x over previous
#include <cuda_runtime.h>
#include <cuda_bf16.h>
#include <math.h>
#include <stdint.h>

#define TT 16
#define NQ 128
#define LATC 128
#define RR 7
#define PP 49
#define CV_K 2432      // 2401 padded to mult of 32
#define X_K 1152       // 1110 padded
#define HID 384
#define EMB 256
#define D_IN 1110

// ---------------------------------------------------------------------------
// Static device scratch
// ---------------------------------------------------------------------------
__device__ float g_pyr0[TT*96*128*LATC];
__device__ float g_pyr1[TT*48*64*LATC];
__device__ float g_pyr2[TT*24*32*LATC];
__device__ float g_pyr3[TT*12*16*LATC];
__device__ __nv_bfloat16 g_tf[(size_t)4*NQ*PP*LATC];
__device__ __nv_bfloat16 g_cv[(size_t)4*TT*NQ*CV_K];
__device__ __nv_bfloat16 g_h1[(size_t)4*TT*NQ*HID];
__device__ float         g_e [(size_t)4*TT*NQ*EMB];
__device__ __nv_bfloat16 g_x [(size_t)NQ*TT*X_K];
__device__ float         g_h2[(size_t)NQ*TT*HID];
__device__ __nv_bfloat16 g_w1t[(size_t)HID*CV_K];
__device__ __nv_bfloat16 g_w2t[(size_t)EMB*HID];
__device__ __nv_bfloat16 g_u1t[(size_t)HID*X_K];
__device__ float g_te[TT*D_IN];
__device__ float g_coords[TT*NQ*2];
__device__ float g_vis [TT*NQ];
__device__ float g_conf[TT*NQ];

__device__ __forceinline__ float geluf(float x) {
    return 0.5f * x * (1.f + erff(x * 0.70710678118654752440f));
}

__device__ __forceinline__ const float* level_ptr(int l, int& Hl, int& Wl) {
    switch (l) {
        case 0: Hl = 96; Wl = 128; return g_pyr0;
        case 1: Hl = 48; Wl = 64;  return g_pyr1;
        case 2: Hl = 24; Wl = 32;  return g_pyr2;
        default:Hl = 12; Wl = 16;  return g_pyr3;
    }
}

// ---------------------------------------------------------------------------
// mma.sync / ldmatrix helpers (baseline PTX, sm_103-safe)
// ---------------------------------------------------------------------------
__device__ __forceinline__ uint32_t smem_u32(const void* p) {
    uint32_t a;
    asm("{ .reg .u64 t; cvta.to.shared.u64 t, %1; cvt.u32.u64 %0, t; }" : "=r"(a) : "l"(p));
    return a;
}
__device__ __forceinline__ void ldsm4(uint32_t* r, uint32_t a) {
    asm volatile("ldmatrix.sync.aligned.m8n8.x4.shared.b16 {%0,%1,%2,%3}, [%4];"
        : "=r"(r[0]), "=r"(r[1]), "=r"(r[2]), "=r"(r[3]) : "r"(a));
}
__device__ __forceinline__ void mma_bf16(float* d, const uint32_t* a, const uint32_t* b) {
    asm volatile("mma.sync.aligned.m16n8k16.row.col.f32.bf16.bf16.f32 "
        "{%0,%1,%2,%3},{%4,%5,%6,%7},{%8,%9},{%0,%1,%2,%3};"
        : "+f"(d[0]), "+f"(d[1]), "+f"(d[2]), "+f"(d[3])
        : "r"(a[0]), "r"(a[1]), "r"(a[2]), "r"(a[3]), "r"(b[0]), "r"(b[1]));
}

// ---------------------------------------------------------------------------
// 4x4/s4 conv + bias + channel L2 norm. Warp-per-pixel x4, block 0 also inits
// ---------------------------------------------------------------------------
__global__ __launch_bounds__(256) void k_conv(const float* __restrict__ video,
                                              const float* __restrict__ w,
                                              const float* __restrict__ b,
                                              const float* __restrict__ q) {
    __shared__ float wsm[48][LATC];
    __shared__ float bsm[LATC];
    int tid = threadIdx.x, lane = tid & 31, warp = tid >> 5;
    for (int i = tid; i < 48 * LATC; i += 256) {
        int c = i / 48, k = i % 48;
        wsm[k][c] = w[i];
    }
    if (tid < LATC) bsm[tid] = b[tid];
    if (blockIdx.x == 0) {
        for (int i = tid; i < TT * NQ; i += 256) {
            int n = i % NQ;
            g_coords[i * 2 + 0] = q[n * 3 + 1] * 0.25f;
            g_coords[i * 2 + 1] = q[n * 3 + 2] * 0.25f;
            g_vis[i]  = 0.f;
            g_conf[i] = 0.f;
        }
    }
    __syncthreads();

#pragma unroll
    for (int px = 0; px < 4; px++) {
        int pix = blockIdx.x * 32 + warp * 4 + px;
        int x = pix & 127; int r = pix >> 7; int y = r % 96; int tf = r / 96;

        float p0, p1 = 0.f;
        {
            int k = lane;
            int ci = k / 16, kk = k % 16, ky = kk / 4, kx = kk % 4;
            p0 = video[(((size_t)tf * 3 + ci) * 384 + (y * 4 + ky)) * 512 + (x * 4 + kx)];
            p0 = 2.f * (p0 * (1.f / 255.f)) - 1.f;
            if (lane < 16) {
                k = 32 + lane;
                ci = k / 16; kk = k % 16; ky = kk / 4; kx = kk % 4;
                p1 = video[(((size_t)tf * 3 + ci) * 384 + (y * 4 + ky)) * 512 + (x * 4 + kx)];
                p1 = 2.f * (p1 * (1.f / 255.f)) - 1.f;
            }
        }
        float acc[4];
#pragma unroll
        for (int j = 0; j < 4; j++) acc[j] = bsm[lane + 32 * j];
#pragma unroll
        for (int k = 0; k < 32; k++) {
            float v = __shfl_sync(0xffffffffu, p0, k);
#pragma unroll
            for (int j = 0; j < 4; j++) acc[j] = fmaf(v, wsm[k][lane + 32 * j], acc[j]);
        }
#pragma unroll
        for (int k = 0; k < 16; k++) {
            float v = __shfl_sync(0xffffffffu, p1, k);
#pragma unroll
            for (int j = 0; j < 4; j++) acc[j] = fmaf(v, wsm[32 + k][lane + 32 * j], acc[j]);
        }
        float s = acc[0] * acc[0] + acc[1] * acc[1] + acc[2] * acc[2] + acc[3] * acc[3];
#pragma unroll
        for (int o = 16; o; o >>= 1) s += __shfl_xor_sync(0xffffffffu, s, o);
        float inv = rsqrtf(fmaxf(s, 1e-12f));
        float* dst = g_pyr0 + (size_t)pix * LATC;
#pragma unroll
        for (int j = 0; j < 4; j++) dst[lane + 32 * j] = acc[j] * inv;
    }
}

// ---------------------------------------------------------------------------
// Hierarchical pools: one block = 8x8 pyr0 patch x 128ch -> l1,l2,l3 cascaded
// ---------------------------------------------------------------------------
__global__ __launch_bounds__(256) void k_pools() {
    __shared__ float sp[8 * 8 * 128];
    __shared__ float s1[4 * 4 * 128];
    __shared__ float s2[2 * 2 * 128];
    int tid = threadIdx.x;
    int bid = blockIdx.x;
    int gx = bid & 15; int r = bid >> 4; int gy = r % 12; int t = r / 12;
    int y0 = gy * 8, x0 = gx * 8;

#pragma unroll
    for (int k = 0; k < 8; k++) {
        int f4 = k * 256 + tid;
        int e = f4 << 2;
        int c = e & 127, dyx = e >> 7;
        int dy = dyx >> 3, dx = dyx & 7;
        *(float4*)&sp[e] = *(const float4*)(g_pyr0 +
            (((size_t)t * 96 + y0 + dy) * 128 + (x0 + dx)) * LATC + c);
    }
    __syncthreads();
#pragma unroll
    for (int k = 0; k < 8; k++) {
        int u = k * 256 + tid;
        int c = u & 127, pix = u >> 7;
        int ly = pix >> 2, lx = pix & 3;
        float v = 0.25f * (sp[((2*ly)*8 + 2*lx)*128 + c] + sp[((2*ly)*8 + 2*lx+1)*128 + c]
                         + sp[((2*ly+1)*8 + 2*lx)*128 + c] + sp[((2*ly+1)*8 + 2*lx+1)*128 + c]);
        s1[u] = v;
        g_pyr1[(((size_t)t * 48 + gy*4 + ly) * 64 + gx*4 + lx) * LATC + c] = v;
    }
    __syncthreads();
#pragma unroll
    for (int k = 0; k < 2; k++) {
        int u = k * 256 + tid;
        int c = u & 127, pix = u >> 7;
        int ly = pix >> 1, lx = pix & 1;
        float v = 0.25f * (s1[((2*ly)*4 + 2*lx)*128 + c] + s1[((2*ly)*4 + 2*lx+1)*128 + c]
                         + s1[((2*ly+1)*4 + 2*lx)*128 + c] + s1[((2*ly+1)*4 + 2*lx+1)*128 + c]);
        s2[u] = v;
        g_pyr2[(((size_t)t * 24 + gy*2 + ly) * 32 + gx*2 + lx) * LATC + c] = v;
    }
    __syncthreads();
    if (tid < 128) {
        float v = 0.25f * (s2[tid] + s2[128 + tid] + s2[256 + tid] + s2[384 + tid]);
        g_pyr3[(((size_t)t * 12 + gy) * 16 + gx) * LATC + tid] = v;
    }
}

// ---------------------------------------------------------------------------
// Template features -> bf16 [l][n][p][c]
// ---------------------------------------------------------------------------
__global__ __launch_bounds__(128) void k_template(const float* __restrict__ q) {
    int n = blockIdx.x, l = blockIdx.y, c = threadIdx.x;
    int Hl, Wl;
    const float* fm = level_ptr(l, Hl, Wl);
    float qf = q[n * 3 + 0];
    float inv = exp2f(-(float)l) * 0.25f;
    float cx = q[n * 3 + 1] * inv, cy = q[n * 3 + 2] * inv;
    float tpos = fminf(fmaxf(qf, 0.f), (float)(TT - 1));
    int t0 = (int)floorf(tpos);
    float wt = tpos - (float)t0;
    int t1 = min(t0 + 1, TT - 1);
    const float* f0 = fm + (size_t)t0 * Hl * Wl * LATC;
    const float* f1 = fm + (size_t)t1 * Hl * Wl * LATC;
    __nv_bfloat16* dst = g_tf + (((size_t)l * NQ + n) * PP) * LATC + c;
    for (int p = 0; p < PP; p++) {
        int h = p / RR, ww = p % RR;
        float px = fminf(fmaxf(cx + (float)(h - 3), 0.f), (float)Wl - 1.f);
        float py = fminf(fmaxf(cy + (float)(ww - 3), 0.f), (float)Hl - 1.f);
        int x0 = (int)floorf(px); float wx = px - (float)x0; int x1 = min(x0 + 1, Wl - 1);
        int y0 = (int)floorf(py); float wy = py - (float)y0; int y1 = min(y0 + 1, Hl - 1);
        int o00 = (y0 * Wl + x0) * LATC + c, o01 = (y0 * Wl + x1) * LATC + c;
        int o10 = (y1 * Wl + x0) * LATC + c, o11 = (y1 * Wl + x1) * LATC + c;
        float v = (1.f - wy) * ((1.f - wx) * f0[o00] + wx * f0[o01])
                +        wy  * ((1.f - wx) * f0[o10] + wx * f0[o11]);
        if (wt > 0.f) {
            float v1 = (1.f - wy) * ((1.f - wx) * f1[o00] + wx * f1[o01])
                     +        wy  * ((1.f - wx) * f1[o10] + wx * f1[o11]);
            v = v * (1.f - wt) + v1 * wt;
        }
        dst[p * LATC] = __float2bfloat16(v);
    }
}

// ---------------------------------------------------------------------------
// Merged prep: 3 weight transposes + 2 pads + time-embedding interp
// ---------------------------------------------------------------------------
#define PR_W1 (HID * CV_K)
#define PR_W2 (EMB * HID)
#define PR_U1 (HID * X_K)
#define PR_CV ((4 * TT * NQ) * (CV_K - 2401))
#define PR_X  ((NQ * TT) * (X_K - D_IN))
#define PR_TE (TT * D_IN)
#define PR_ALL (PR_W1 + PR_W2 + PR_U1 + PR_CV + PR_X + PR_TE)

__global__ void k_prep(const float* __restrict__ fc1_w,
                       const float* __restrict__ fc2_w,
                       const float* __restrict__ up_w1,
                       const float* __restrict__ emb) {
    int i = blockIdx.x * blockDim.x + threadIdx.x;
    if (i < PR_W1) {
        int n = i / CV_K, k = i - n * CV_K;
        g_w1t[i] = __float2bfloat16((k < 2401) ? fc1_w[(size_t)k * HID + n] : 0.f);
        return;
    }
    i -= PR_W1;
    if (i < PR_W2) {
        int n = i / HID, k = i - n * HID;
        g_w2t[i] = __float2bfloat16(fc2_w[(size_t)k * EMB + n]);
        return;
    }
    i -= PR_W2;
    if (i < PR_U1) {
        int n = i / X_K, k = i - n * X_K;
        g_u1t[i] = __float2bfloat16((k < D_IN) ? up_w1[(size_t)k * HID + n] : 0.f);
        return;
    }
    i -= PR_U1;
    if (i < PR_CV) {
        int cw = CV_K - 2401;
        int r = i / cw, c = i - r * cw;
        g_cv[(size_t)r * CV_K + 2401 + c] = __float2bfloat16(0.f);
        return;
    }
    i -= PR_CV;
    if (i < PR_X) {
        int cw = X_K - D_IN;
        int r = i / cw, c = i - r * cw;
        g_x[(size_t)r * X_K + D_IN + c] = __float2bfloat16(0.f);
        return;
    }
    i -= PR_X;
    if (i < PR_TE) {
        int t = i / D_IN, d = i % D_IN;
        float j = ((float)t + 0.5f) * (50.f / 16.f) - 0.5f;
        j = fminf(fmaxf(j, 0.f), 49.f);
        int j0 = (int)floorf(j);
        int j1 = min(j0 + 1, 49);
        float w = j - (float)j0;
        g_te[i] = emb[j0 * D_IN + d] * (1.f - w) + emb[j1 * D_IN + d] * w;
    }
}

// ---------------------------------------------------------------------------
// Fused bilinear sample + 49x49x128 correlation via mma.sync.
// R9 gather + MMA, with smem-staged coalesced epilogue store.
// ---------------------------------------------------------------------------
#define CS 136

__global__ __launch_bounds__(256) void k_corr_mma() {
    __shared__ __nv_bfloat16 cf[64 * CS];
    __shared__ __nv_bfloat16 tf[64 * CS];
    __shared__ __nv_bfloat16 stage[2408];    // 49*49=2401, padded to 8
    __shared__ int   sO[PP][4];
    __shared__ float sW[PP][2];
    int n = blockIdx.x, t = blockIdx.y, l = blockIdx.z;
    int tid = threadIdx.x, lane = tid & 31, w = tid >> 5;
    int Hl, Wl;
    const float* fm = level_ptr(l, Hl, Wl);
    fm += (size_t)t * Hl * Wl * LATC;

    if (tid < PP) {
        float inv = exp2f(-(float)l);
        float cx = g_coords[(t * NQ + n) * 2 + 0] * inv;
        float cy = g_coords[(t * NQ + n) * 2 + 1] * inv;
        int h = tid / RR, ww = tid % RR;
        float px = fminf(fmaxf(cx + (float)(h - 3), 0.f), (float)Wl - 1.f);
        float py = fminf(fmaxf(cy + (float)(ww - 3), 0.f), (float)Hl - 1.f);
        int x0 = (int)floorf(px); float wx = px - (float)x0; int x1 = min(x0 + 1, Wl - 1);
        int y0 = (int)floorf(py); float wy = py - (float)y0; int y1 = min(y0 + 1, Hl - 1);
        sO[tid][0] = (y0 * Wl + x0) * LATC;
        sO[tid][1] = (y0 * Wl + x1) * LATC;
        sO[tid][2] = (y1 * Wl + x0) * LATC;
        sO[tid][3] = (y1 * Wl + x1) * LATC;
        sW[tid][0] = wx; sW[tid][1] = wy;
    }
    for (int i = tid; i < 15 * CS; i += 256) {
        cf[49 * CS + i] = __float2bfloat16(0.f);
        tf[49 * CS + i] = __float2bfloat16(0.f);
    }
    const __nv_bfloat16* tfg = g_tf + (((size_t)l * NQ + n) * PP) * LATC;
    for (int i = tid; i < PP * 16; i += 256) {
        int p = i >> 4, c8 = (i & 15) << 3;
        *(uint4*)&tf[p * CS + c8] = *(const uint4*)(tfg + p * LATC + c8);
    }
    __syncthreads();
    for (int i = tid; i < PP * 32; i += 256) {
        int p = i >> 5, c4 = (i & 31) << 2;
        float wx = sW[p][0], wy = sW[p][1];
        float w00 = (1.f - wy) * (1.f - wx), w01 = (1.f - wy) * wx;
        float w10 = wy * (1.f - wx),         w11 = wy * wx;
        float4 v00 = *(const float4*)(fm + sO[p][0] + c4);
        float4 v01 = *(const float4*)(fm + sO[p][1] + c4);
        float4 v10 = *(const float4*)(fm + sO[p][2] + c4);
        float4 v11 = *(const float4*)(fm + sO[p][3] + c4);
        float r0 = w00 * v00.x + w01 * v01.x + w10 * v10.x + w11 * v11.x;
        float r1 = w00 * v00.y + w01 * v01.y + w10 * v10.y + w11 * v11.y;
        float r2 = w00 * v00.z + w01 * v01.z + w10 * v10.z + w11 * v11.z;
        float r3 = w00 * v00.w + w01 * v01.w + w10 * v10.w + w11 * v11.w;
        __nv_bfloat162* dst = (__nv_bfloat162*)&cf[p * CS + c4];
        dst[0] = __floats2bfloat162_rn(r0, r1);
        dst[1] = __floats2bfloat162_rn(r2, r3);
    }
    __syncthreads();

    int m2 = w >> 2, nw = w & 3;
    float acc[2][2][4] = {};
#pragma unroll
    for (int ks = 0; ks < 8; ks++) {
        uint32_t b[2][2];
        {
            uint32_t rr[4];
            uint32_t addr = smem_u32(&tf[((nw << 4) + ((lane >> 4) << 3) + (lane & 7)) * CS
                                         + (ks << 4) + (((lane >> 3) & 1) << 3)]);
            ldsm4(rr, addr);
            b[0][0] = rr[0]; b[0][1] = rr[1]; b[1][0] = rr[2]; b[1][1] = rr[3];
        }
#pragma unroll
        for (int f = 0; f < 2; f++) {
            int fa = (m2 << 1) + f;
            uint32_t a[4];
            ldsm4(a, smem_u32(&cf[((fa << 4) + (lane & 15)) * CS + (ks << 4) + ((lane >> 4) << 3)]));
            mma_bf16(acc[f][0], a, b[0]);
            mma_bf16(acc[f][1], a, b[1]);
        }
    }

    // stage results in smem (predicated cheap STS), then coalesced STG
#pragma unroll
    for (int f = 0; f < 2; f++) {
        int m0 = ((m2 << 1) + f << 4) + (lane >> 2);
#pragma unroll
        for (int g = 0; g < 2; g++) {
            int nn = (nw << 4) + (g << 3) + ((lane & 3) << 1);
            if (nn < PP) {
                if (m0 < PP) stage[m0 * PP + nn] = __float2bfloat16(acc[f][g][0]);
                if (m0 + 8 < PP) stage[(m0 + 8) * PP + nn] = __float2bfloat16(acc[f][g][2]);
                if (nn + 1 < PP) {
                    if (m0 < PP) stage[m0 * PP + nn + 1] = __float2bfloat16(acc[f][g][1]);
                    if (m0 + 8 < PP) stage[(m0 + 8) * PP + nn + 1] = __float2bfloat16(acc[f][g][3]);
                }
            }
        }
    }
    __syncthreads();
    __nv_bfloat16* cv = g_cv + ((size_t)((l * TT + t) * NQ + n)) * CV_K;
    // 2401 bf16: 300 uint4 (2400) + 1 scalar
    for (int i = tid; i < 300; i += 256)
        *(uint4*)(cv + (i << 3)) = *(const uint4*)(stage + (i << 3));
    if (tid == 0) cv[2400] = stage[2400];
}

// ---------------------------------------------------------------------------
// bf16 mma.sync GEMM, 128x128 CTA tile (R9), LDG->compute->STS pipeline.
// ---------------------------------------------------------------------------
#define GST 40

__global__ __launch_bounds__(256) void k_gemm_bf(const __nv_bfloat16* __restrict__ A,
                                                 const __nv_bfloat16* __restrict__ Bt,
                                                 const float* __restrict__ bias,
                                                 void* __restrict__ Cv,
                                                 int M, int N, int K, int act, int outbf) {
    __shared__ __nv_bfloat16 As[2][128 * GST];
    __shared__ __nv_bfloat16 Bs[2][128 * GST];
    int tid = threadIdx.x, lane = tid & 31, warp = tid >> 5;
    int wm = (warp & 1) << 6, wn = (warp >> 1) << 5;
    int row0 = blockIdx.y << 7, col0 = blockIdx.x << 7;
    const __nv_bfloat16* Ag = A  + (size_t)row0 * K;
    const __nv_bfloat16* Bg = Bt + (size_t)col0 * K;

    int r1 = tid >> 2, c1 = (tid & 3) << 3;
    int r2 = (tid + 256) >> 2, c2 = ((tid + 256) & 3) << 3;

    *(uint4*)(As[0] + r1 * GST + c1) = *(const uint4*)(Ag + (size_t)r1 * K + c1);
    *(uint4*)(As[0] + r2 * GST + c2) = *(const uint4*)(Ag + (size_t)r2 * K + c2);
    *(uint4*)(Bs[0] + r1 * GST + c1) = *(const uint4*)(Bg + (size_t)r1 * K + c1);
    *(uint4*)(Bs[0] + r2 * GST + c2) = *(const uint4*)(Bg + (size_t)r2 * K + c2);
    __syncthreads();

    float acc[4][4][4] = {};
    int nk = K >> 5;
    for (int i = 0; i < nk; i++) {
        int s = i & 1;
        uint4 ra0, ra1, rb0, rb1;
        bool pre = (i + 1 < nk);
        if (pre) {
            int k0 = (i + 1) << 5;
            ra0 = *(const uint4*)(Ag + (size_t)r1 * K + k0 + c1);
            ra1 = *(const uint4*)(Ag + (size_t)r2 * K + k0 + c2);
            rb0 = *(const uint4*)(Bg + (size_t)r1 * K + k0 + c1);
            rb1 = *(const uint4*)(Bg + (size_t)r2 * K + k0 + c2);
        }
#pragma unroll
        for (int ks = 0; ks < 2; ks++) {
            uint32_t b[4][2];
#pragma unroll
            for (int g = 0; g < 2; g++) {
                uint32_t rr[4];
                uint32_t addr = smem_u32(Bs[s] + (wn + (g << 4) + ((lane >> 4) << 3) + (lane & 7)) * GST
                                         + (ks << 4) + (((lane >> 3) & 1) << 3));
                ldsm4(rr, addr);
                b[g * 2][0] = rr[0]; b[g * 2][1] = rr[1];
                b[g * 2 + 1][0] = rr[2]; b[g * 2 + 1][1] = rr[3];
            }
#pragma unroll
            for (int f = 0; f < 4; f++) {
                uint32_t a[4];
                ldsm4(a, smem_u32(As[s] + (wm + (f << 4) + (lane & 15)) * GST
                                  + (ks << 4) + ((lane >> 4) << 3)));
#pragma unroll
                for (int g = 0; g < 4; g++) mma_bf16(acc[f][g], a, b[g]);
            }
        }
        if (pre) {
            int s2 = s ^ 1;
            *(uint4*)(As[s2] + r1 * GST + c1) = ra0;
            *(uint4*)(As[s2] + r2 * GST + c2) = ra1;
            *(uint4*)(Bs[s2] + r1 * GST + c1) = rb0;
            *(uint4*)(Bs[s2] + r2 * GST + c2) = rb1;
        }
        __syncthreads();
    }
#pragma unroll
    for (int f = 0; f < 4; f++) {
        int m = row0 + wm + (f << 4) + (lane >> 2);
#pragma unroll
        for (int g = 0; g < 4; g++) {
            int nn = col0 + wn + (g << 3) + ((lane & 3) << 1);
            float b0 = bias[nn], b1 = bias[nn + 1];
            float v0 = acc[f][g][0] + b0, v1 = acc[f][g][1] + b1;
            float v2 = acc[f][g][2] + b0, v3 = acc[f][g][3] + b1;
            if (act) { v0 = geluf(v0); v1 = geluf(v1); v2 = geluf(v2); v3 = geluf(v3); }
            if (outbf) {
                __nv_bfloat16* C = (__nv_bfloat16*)Cv;
                C[(size_t)m * N + nn] = __float2bfloat16(v0);
                C[(size_t)m * N + nn + 1] = __float2bfloat16(v1);
                C[(size_t)(m + 8) * N + nn] = __float2bfloat16(v2);
                C[(size_t)(m + 8) * N + nn + 1] = __float2bfloat16(v3);
            } else {
                float* C = (float*)Cv;
                C[(size_t)m * N + nn] = v0;
                C[(size_t)m * N + nn + 1] = v1;
                C[(size_t)(m + 8) * N + nn] = v2;
                C[(size_t)(m + 8) * N + nn + 1] = v3;
            }
        }
    }
}

// ---------------------------------------------------------------------------
// bf16 mma.sync GEMM, 64x64 CTA tile (small-grid shapes: up-GEMM).
// ---------------------------------------------------------------------------
__global__ __launch_bounds__(128) void k_gemm64(const __nv_bfloat16* __restrict__ A,
                                                const __nv_bfloat16* __restrict__ Bt,
                                                const float* __restrict__ bias,
                                                void* __restrict__ Cv,
                                                int M, int N, int K, int act, int outbf) {
    __shared__ __nv_bfloat16 As[2][64 * GST];
    __shared__ __nv_bfloat16 Bs[2][64 * GST];
    int tid = threadIdx.x, lane = tid & 31, warp = tid >> 5;
    int wm = (warp & 1) << 5, wn = (warp >> 1) << 5;
    int row0 = blockIdx.y << 6, col0 = blockIdx.x << 6;
    const __nv_bfloat16* Ag = A  + (size_t)row0 * K;
    const __nv_bfloat16* Bg = Bt + (size_t)col0 * K;

    int r1 = tid >> 2, c1 = (tid & 3) << 3;
    int r2 = (tid + 128) >> 2, c2 = ((tid + 128) & 3) << 3;

    *(uint4*)(As[0] + r1 * GST + c1) = *(const uint4*)(Ag + (size_t)r1 * K + c1);
    *(uint4*)(As[0] + r2 * GST + c2) = *(const uint4*)(Ag + (size_t)r2 * K + c2);
    *(uint4*)(Bs[0] + r1 * GST + c1) = *(const uint4*)(Bg + (size_t)r1 * K + c1);
    *(uint4*)(Bs[0] + r2 * GST + c2) = *(const uint4*)(Bg + (size_t)r2 * K + c2);
    __syncthreads();

    float acc[2][4][4] = {};
    int nk = K >> 5;
    for (int i = 0; i < nk; i++) {
        int s = i & 1;
        uint4 ra0, ra1, rb0, rb1;
        bool pre = (i + 1 < nk);
        if (pre) {
            int k0 = (i + 1) << 5;
            ra0 = *(const uint4*)(Ag + (size_t)r1 * K + k0 + c1);
            ra1 = *(const uint4*)(Ag + (size_t)r2 * K + k0 + c2);
            rb0 = *(const uint4*)(Bg + (size_t)r1 * K + k0 + c1);
            rb1 = *(const uint4*)(Bg + (size_t)r2 * K + k0 + c2);
        }
#pragma unroll
        for (int ks = 0; ks < 2; ks++) {
            uint32_t b[4][2];
#pragma unroll
            for (int g = 0; g < 2; g++) {
                uint32_t rr[4];
                uint32_t addr = smem_u32(Bs[s] + (wn + (g << 4) + ((lane >> 4) << 3) + (lane & 7)) * GST
                                         + (ks << 4) + (((lane >> 3) & 1) << 3));
                ldsm4(rr, addr);
                b[g * 2][0] = rr[0]; b[g * 2][1] = rr[1];
                b[g * 2 + 1][0] = rr[2]; b[g * 2 + 1][1] = rr[3];
            }
#pragma unroll
            for (int f = 0; f < 2; f++) {
                uint32_t a[4];
                ldsm4(a, smem_u32(As[s] + (wm + (f << 4) + (lane & 15)) * GST
                                  + (ks << 4) + ((lane >> 4) << 3)));
#pragma unroll
                for (int g = 0; g < 4; g++) mma_bf16(acc[f][g], a, b[g]);
            }
        }
        if (pre) {
            int s2 = s ^ 1;
            *(uint4*)(As[s2] + r1 * GST + c1) = ra0;
            *(uint4*)(As[s2] + r2 * GST + c2) = ra1;
            *(uint4*)(Bs[s2] + r1 * GST + c1) = rb0;
            *(uint4*)(Bs[s2] + r2 * GST + c2) = rb1;
        }
        __syncthreads();
    }
#pragma unroll
    for (int f = 0; f < 2; f++) {
        int m = row0 + wm + (f << 4) + (lane >> 2);
#pragma unroll
        for (int g = 0; g < 4; g++) {
            int nn = col0 + wn + (g << 3) + ((lane & 3) << 1);
            float b0 = bias[nn], b1 = bias[nn + 1];
            float v0 = acc[f][g][0] + b0, v1 = acc[f][g][1] + b1;
            float v2 = acc[f][g][2] + b0, v3 = acc[f][g][3] + b1;
            if (act) { v0 = geluf(v0); v1 = geluf(v1); v2 = geluf(v2); v3 = geluf(v3); }
            if (outbf) {
                __nv_bfloat16* C = (__nv_bfloat16*)Cv;
                C[(size_t)m * N + nn] = __float2bfloat16(v0);
                C[(size_t)m * N + nn + 1] = __float2bfloat16(v1);
                C[(size_t)(m + 8) * N + nn] = __float2bfloat16(v2);
                C[(size_t)(m + 8) * N + nn + 1] = __float2bfloat16(v3);
            } else {
                float* C = (float*)Cv;
                C[(size_t)m * N + nn] = v0;
                C[(size_t)m * N + nn + 1] = v1;
                C[(size_t)(m + 8) * N + nn] = v2;
                C[(size_t)(m + 8) * N + nn + 1] = v3;
            }
        }
    }
}

// ---------------------------------------------------------------------------
// Assemble update-MLP input (bf16)
// ---------------------------------------------------------------------------
__global__ __launch_bounds__(128) void k_assemble() {
    int row = blockIdx.x;
    int n = row >> 4, t = row & 15;
    int tid = threadIdx.x;
    __shared__ float x4[4];
    if (tid == 0) {
        float cx = g_coords[(t * NQ + n) * 2 + 0];
        float cy = g_coords[(t * NQ + n) * 2 + 1];
        float rfx = 0.f, rfy = 0.f, rbx = 0.f, rby = 0.f;
        if (t < TT - 1) {
            rfx = (cx - g_coords[((t + 1) * NQ + n) * 2 + 0]) * (1.f / 128.f);
            rfy = (cy - g_coords[((t + 1) * NQ + n) * 2 + 1]) * (1.f / 96.f);
        }
        if (t > 0) {
            rbx = (cx - g_coords[((t - 1) * NQ + n) * 2 + 0]) * (1.f / 128.f);
            rby = (cy - g_coords[((t - 1) * NQ + n) * 2 + 1]) * (1.f / 96.f);
        }
        x4[0] = rfx; x4[1] = rfy; x4[2] = rbx; x4[3] = rby;
    }
    __syncthreads();
    __nv_bfloat16* dst = g_x + (size_t)row * X_K;
    for (int d = tid; d < D_IN; d += 128) {
        float v;
        if (d == 0) v = g_vis[t * NQ + n];
        else if (d == 1) v = g_conf[t * NQ + n];
        else if (d < 2 + 4 * EMB) {
            int qd = d - 2;
            int l = qd >> 8, k = qd & 255;
            v = g_e[(((size_t)(l * TT + t) * NQ + n) << 8) + k];
        } else {
            int j = d - (2 + 4 * EMB);
            if (j < 4) v = x4[j];
            else if (j < 44) {
                int s = (j - 4) >> 2, dd = (j - 4) & 3;
                v = sinf(x4[dd] * exp2f((float)s));
            } else {
                int s = (j - 44) >> 2, dd = (j - 44) & 3;
                v = cosf(x4[dd] * exp2f((float)s));
            }
        }
        dst[d] = __float2bfloat16(v + g_te[t * D_IN + d]);
    }
}

// ---------------------------------------------------------------------------
// Final tiny GEMV (384->4) + state update
// ---------------------------------------------------------------------------
__global__ __launch_bounds__(128) void k_update(const float* __restrict__ w2,
                                                const float* __restrict__ b2) {
    int row = blockIdx.x;
    int tid = threadIdx.x;
    const float* hrow = g_h2 + (size_t)row * HID;
    float a0 = 0.f, a1 = 0.f, a2 = 0.f, a3 = 0.f;
    for (int i = tid; i < HID; i += 128) {
        float h = hrow[i];
        const float* w = w2 + i * 4;
        a0 = fmaf(h, w[0], a0); a1 = fmaf(h, w[1], a1);
        a2 = fmaf(h, w[2], a2); a3 = fmaf(h, w[3], a3);
    }
#pragma unroll
    for (int o = 16; o; o >>= 1) {
        a0 += __shfl_xor_sync(0xffffffffu, a0, o);
        a1 += __shfl_xor_sync(0xffffffffu, a1, o);
        a2 += __shfl_xor_sync(0xffffffffu, a2, o);
        a3 += __shfl_xor_sync(0xffffffffu, a3, o);
    }
    __shared__ float red[4][4];
    int warp = tid >> 5, lane = tid & 31;
    if (lane == 0) { red[warp][0] = a0; red[warp][1] = a1; red[warp][2] = a2; red[warp][3] = a3; }
    __syncthreads();
    if (tid == 0) {
        float d0 = red[0][0] + red[1][0] + red[2][0] + red[3][0] + b2[0];
        float d1 = red[0][1] + red[1][1] + red[2][1] + red[3][1] + b2[1];
        float d2 = red[0][2] + red[1][2] + red[2][2] + red[3][2] + b2[2];
        float d3 = red[0][3] + red[1][3] + red[2][3] + red[3][3] + b2[3];
        int n = row >> 4, t = row & 15;
        g_coords[(t * NQ + n) * 2 + 0] += d0;
        g_coords[(t * NQ + n) * 2 + 1] += d1;
        g_vis[t * NQ + n]  += d2;
        g_conf[t * NQ + n] += d3;
    }
}

// ---------------------------------------------------------------------------
// Outputs
// ---------------------------------------------------------------------------
__global__ void k_output(float* __restrict__ out) {
    int i = blockIdx.x * blockDim.x + threadIdx.x;
    if (i >= 8192) return;
    if (i < 4096) out[i] = g_coords[i] * 4.f;
    else if (i < 6144) out[i] = 1.f / (1.f + expf(-g_vis[i - 4096]));
    else out[i] = 1.f / (1.f + expf(-g_conf[i - 6144]));
}

// ---------------------------------------------------------------------------
// Launch. Order: conv(1) pools(2) template(3) corr(4, profiled) prep(5) ...
// ---------------------------------------------------------------------------
extern "C" void kernel_launch(void* const* d_in, const int* in_sizes, int n_in,
                              void* d_out, int out_size) {
    const float* video   = (const float*)d_in[0];
    const float* queries = (const float*)d_in[1];
    const float* fnet_w  = (const float*)d_in[2];
    const float* fnet_b  = (const float*)d_in[3];
    const float* fc1_w   = (const float*)d_in[4];
    const float* fc1_b   = (const float*)d_in[5];
    const float* fc2_w   = (const float*)d_in[6];
    const float* fc2_b   = (const float*)d_in[7];
    const float* up_w1   = (const float*)d_in[8];
    const float* up_b1   = (const float*)d_in[9];
    const float* up_w2   = (const float*)d_in[10];
    const float* up_b2   = (const float*)d_in[11];
    const float* time_emb= (const float*)d_in[12];
    float* out = (float*)d_out;

    __nv_bfloat16 *p_cv, *p_h1, *p_x, *p_w1t, *p_w2t, *p_u1t;
    float *p_e, *p_h2;
    cudaGetSymbolAddress((void**)&p_cv,  g_cv);
    cudaGetSymbolAddress((void**)&p_h1,  g_h1);
    cudaGetSymbolAddress((void**)&p_e,   g_e);
    cudaGetSymbolAddress((void**)&p_x,   g_x);
    cudaGetSymbolAddress((void**)&p_h2,  g_h2);
    cudaGetSymbolAddress((void**)&p_w1t, g_w1t);
    cudaGetSymbolAddress((void**)&p_w2t, g_w2t);
    cudaGetSymbolAddress((void**)&p_u1t, g_u1t);

    const int M1 = 4 * TT * NQ;   // 8192
    const int M3 = NQ * TT;       // 2048

    k_conv<<<TT * 96 * 128 / 32, 256>>>(video, fnet_w, fnet_b, queries);  // 1
    k_pools<<<TT * 12 * 16, 256>>>();                                     // 2
    k_template<<<dim3(NQ, 4), 128>>>(queries);                            // 3

    for (int it = 0; it < 4; it++) {
        k_corr_mma<<<dim3(NQ, TT, 4), 256>>>();                           // 4 on it=0
        if (it == 0)
            k_prep<<<(PR_ALL + 255) / 256, 256>>>(fc1_w, fc2_w, up_w1, time_emb);
        k_gemm_bf<<<dim3(HID / 128, M1 / 128), 256>>>(p_cv, p_w1t, fc1_b, p_h1, M1, HID, CV_K, 1, 1);
        k_gemm_bf<<<dim3(EMB / 128, M1 / 128), 256>>>(p_h1, p_w2t, fc2_b, p_e, M1, EMB, HID, 0, 0);
        k_assemble<<<M3, 128>>>();
        k_gemm64<<<dim3(HID / 64, M3 / 64), 128>>>(p_x, p_u1t, up_b1, p_h2, M3, HID, X_K, 1, 0);
        k_update<<<M3, 128>>>(up_w2, up_b2);
    }
    k_output<<<(8192 + 255) / 256, 256>>>(out);
}

// round 17
// speedup vs baseline: 1.3026x; 1.1557x over previous
#include <cuda_runtime.h>
#include <cuda_bf16.h>
#include <math.h>
#include <stdint.h>

#define TT 16
#define NQ 128
#define LATC 128
#define RR 7
#define PP 49
#define CV_K 2432      // 2401 padded to mult of 32
#define X_K 1152       // 1110 padded
#define HID 384
#define EMB 256
#define D_IN 1110

// ---------------------------------------------------------------------------
// Static device scratch
// ---------------------------------------------------------------------------
__device__ float g_pyr0[TT*96*128*LATC];
__device__ float g_pyr1[TT*48*64*LATC];
__device__ float g_pyr2[TT*24*32*LATC];
__device__ float g_pyr3[TT*12*16*LATC];
__device__ __nv_bfloat16 g_tf[(size_t)4*NQ*PP*LATC];
__device__ __nv_bfloat16 g_cv[(size_t)4*TT*NQ*CV_K];
__device__ __nv_bfloat16 g_h1[(size_t)4*TT*NQ*HID];
__device__ __nv_bfloat16 g_x [(size_t)NQ*TT*X_K];
__device__ float         g_h2[(size_t)NQ*TT*HID];
__device__ __nv_bfloat16 g_w1t[(size_t)HID*CV_K];
__device__ __nv_bfloat16 g_w2t[(size_t)EMB*HID];
__device__ __nv_bfloat16 g_u1t[(size_t)HID*X_K];
__device__ float g_te[TT*D_IN];
__device__ float g_coords[TT*NQ*2];
__device__ float g_vis [TT*NQ];
__device__ float g_conf[TT*NQ];

__device__ __forceinline__ float geluf(float x) {
    return 0.5f * x * (1.f + erff(x * 0.70710678118654752440f));
}

__device__ __forceinline__ const float* level_ptr(int l, int& Hl, int& Wl) {
    switch (l) {
        case 0: Hl = 96; Wl = 128; return g_pyr0;
        case 1: Hl = 48; Wl = 64;  return g_pyr1;
        case 2: Hl = 24; Wl = 32;  return g_pyr2;
        default:Hl = 12; Wl = 16;  return g_pyr3;
    }
}

// ---------------------------------------------------------------------------
// mma.sync / ldmatrix helpers (baseline PTX, sm_103-safe)
// ---------------------------------------------------------------------------
__device__ __forceinline__ uint32_t smem_u32(const void* p) {
    uint32_t a;
    asm("{ .reg .u64 t; cvta.to.shared.u64 t, %1; cvt.u32.u64 %0, t; }" : "=r"(a) : "l"(p));
    return a;
}
__device__ __forceinline__ void ldsm4(uint32_t* r, uint32_t a) {
    asm volatile("ldmatrix.sync.aligned.m8n8.x4.shared.b16 {%0,%1,%2,%3}, [%4];"
        : "=r"(r[0]), "=r"(r[1]), "=r"(r[2]), "=r"(r[3]) : "r"(a));
}
__device__ __forceinline__ void mma_bf16(float* d, const uint32_t* a, const uint32_t* b) {
    asm volatile("mma.sync.aligned.m16n8k16.row.col.f32.bf16.bf16.f32 "
        "{%0,%1,%2,%3},{%4,%5,%6,%7},{%8,%9},{%0,%1,%2,%3};"
        : "+f"(d[0]), "+f"(d[1]), "+f"(d[2]), "+f"(d[3])
        : "r"(a[0]), "r"(a[1]), "r"(a[2]), "r"(a[3]), "r"(b[0]), "r"(b[1]));
}
__device__ __forceinline__ void mma_tf32(float* d, const uint32_t* a, const uint32_t* b) {
    asm volatile("mma.sync.aligned.m16n8k8.row.col.f32.tf32.tf32.f32 "
        "{%0,%1,%2,%3},{%4,%5,%6,%7},{%8,%9},{%0,%1,%2,%3};"
        : "+f"(d[0]), "+f"(d[1]), "+f"(d[2]), "+f"(d[3])
        : "r"(a[0]), "r"(a[1]), "r"(a[2]), "r"(a[3]), "r"(b[0]), "r"(b[1]));
}
__device__ __forceinline__ uint32_t f2tf32(float f) {
    uint32_t r; asm("cvt.rna.tf32.f32 %0, %1;" : "=r"(r) : "f"(f)); return r;
}

// ---------------------------------------------------------------------------
// Conv via tf32 implicit GEMM. Block = (t, y): 128 pixels x 128 ch, K=48.
// A: K-major [48][136] tf32; B: N-major [128][52] tf32. 8 warps x M16 tiles.
// Fused bias + channel L2 norm. Block 0 also inits tracker state.
// ---------------------------------------------------------------------------
#define CVA_ST 136
#define CVB_ST 52
#define CONV_SMEM ((48 * CVA_ST + 128 * CVB_ST + 128) * 4)

__global__ __launch_bounds__(256) void k_conv_tc(const float* __restrict__ video,
                                                 const float* __restrict__ w,
                                                 const float* __restrict__ b,
                                                 const float* __restrict__ q) {
    extern __shared__ uint32_t csm[];
    uint32_t* As = csm;                    // [48][CVA_ST]
    uint32_t* Bs = csm + 48 * CVA_ST;      // [128][CVB_ST]
    float*    bsm = (float*)(Bs + 128 * CVB_ST);
    int tid = threadIdx.x, lane = tid & 31, warp = tid >> 5;
    int bidx = blockIdx.x;
    int y = bidx % 96, t = bidx / 96;

    if (blockIdx.x == 0) {
        for (int i = tid; i < TT * NQ; i += 256) {
            int n = i % NQ;
            g_coords[i * 2 + 0] = q[n * 3 + 1] * 0.25f;
            g_coords[i * 2 + 1] = q[n * 3 + 2] * 0.25f;
            g_vis[i]  = 0.f;
            g_conf[i] = 0.f;
        }
    }
    // B: w[c][k] -> Bs[c][k]
    for (int i = tid; i < 128 * 48; i += 256) {
        int c = i / 48, k = i - c * 48;
        Bs[c * CVB_ST + k] = f2tf32(w[i]);
    }
    if (tid < 128) bsm[tid] = b[tid];
    // A: 12 source rows (ci,ky) x 128 float4 -> As[k][x]
    for (int i = tid; i < 12 * 128; i += 256) {
        int r = i >> 7, x = i & 127;
        int ci = r >> 2, ky = r & 3;
        float4 v = *(const float4*)(video + (((size_t)t * 3 + ci) * 384 + (y * 4 + ky)) * 512 + x * 4);
        int kb = ci * 16 + ky * 4;
        As[(kb + 0) * CVA_ST + x] = f2tf32(2.f * (v.x * (1.f / 255.f)) - 1.f);
        As[(kb + 1) * CVA_ST + x] = f2tf32(2.f * (v.y * (1.f / 255.f)) - 1.f);
        As[(kb + 2) * CVA_ST + x] = f2tf32(2.f * (v.z * (1.f / 255.f)) - 1.f);
        As[(kb + 3) * CVA_ST + x] = f2tf32(2.f * (v.w * (1.f / 255.f)) - 1.f);
    }
    __syncthreads();

    int m0 = warp << 4;
    int g = lane >> 2, tg = lane & 3;
    float acc[16][4] = {};
#pragma unroll
    for (int ks = 0; ks < 6; ks++) {
        int k0 = ks << 3;
        uint32_t a[4];
        a[0] = As[(k0 + tg) * CVA_ST + m0 + g];
        a[1] = As[(k0 + tg) * CVA_ST + m0 + g + 8];
        a[2] = As[(k0 + tg + 4) * CVA_ST + m0 + g];
        a[3] = As[(k0 + tg + 4) * CVA_ST + m0 + g + 8];
#pragma unroll
        for (int nf = 0; nf < 16; nf++) {
            uint32_t bb[2];
            bb[0] = Bs[((nf << 3) + g) * CVB_ST + k0 + tg];
            bb[1] = Bs[((nf << 3) + g) * CVB_ST + k0 + tg + 4];
            mma_tf32(acc[nf], a, bb);
        }
    }
    // bias + sum of squares
    float s1 = 0.f, s2 = 0.f;
#pragma unroll
    for (int nf = 0; nf < 16; nf++) {
        int n0 = (nf << 3) + (tg << 1);
        float b0 = bsm[n0], b1 = bsm[n0 + 1];
        acc[nf][0] += b0; acc[nf][1] += b1;
        acc[nf][2] += b0; acc[nf][3] += b1;
        s1 += acc[nf][0] * acc[nf][0] + acc[nf][1] * acc[nf][1];
        s2 += acc[nf][2] * acc[nf][2] + acc[nf][3] * acc[nf][3];
    }
    s1 += __shfl_xor_sync(0xffffffffu, s1, 1);
    s1 += __shfl_xor_sync(0xffffffffu, s1, 2);
    s2 += __shfl_xor_sync(0xffffffffu, s2, 1);
    s2 += __shfl_xor_sync(0xffffffffu, s2, 2);
    float inv1 = rsqrtf(fmaxf(s1, 1e-12f));
    float inv2 = rsqrtf(fmaxf(s2, 1e-12f));
    size_t rowbase = ((size_t)(t * 96 + y) * 128);
    float* d1 = g_pyr0 + (rowbase + m0 + g) * LATC;
    float* d2 = g_pyr0 + (rowbase + m0 + g + 8) * LATC;
#pragma unroll
    for (int nf = 0; nf < 16; nf++) {
        int n0 = (nf << 3) + (tg << 1);
        *(float2*)(d1 + n0) = make_float2(acc[nf][0] * inv1, acc[nf][1] * inv1);
        *(float2*)(d2 + n0) = make_float2(acc[nf][2] * inv2, acc[nf][3] * inv2);
    }
}

// ---------------------------------------------------------------------------
// Hierarchical pools: one block = 8x8 pyr0 patch x 128ch -> l1,l2,l3 cascaded
// ---------------------------------------------------------------------------
__global__ __launch_bounds__(256) void k_pools() {
    __shared__ float sp[8 * 8 * 128];
    __shared__ float s1[4 * 4 * 128];
    __shared__ float s2[2 * 2 * 128];
    int tid = threadIdx.x;
    int bid = blockIdx.x;
    int gx = bid & 15; int r = bid >> 4; int gy = r % 12; int t = r / 12;
    int y0 = gy * 8, x0 = gx * 8;

#pragma unroll
    for (int k = 0; k < 8; k++) {
        int f4 = k * 256 + tid;
        int e = f4 << 2;
        int c = e & 127, dyx = e >> 7;
        int dy = dyx >> 3, dx = dyx & 7;
        *(float4*)&sp[e] = *(const float4*)(g_pyr0 +
            (((size_t)t * 96 + y0 + dy) * 128 + (x0 + dx)) * LATC + c);
    }
    __syncthreads();
#pragma unroll
    for (int k = 0; k < 8; k++) {
        int u = k * 256 + tid;
        int c = u & 127, pix = u >> 7;
        int ly = pix >> 2, lx = pix & 3;
        float v = 0.25f * (sp[((2*ly)*8 + 2*lx)*128 + c] + sp[((2*ly)*8 + 2*lx+1)*128 + c]
                         + sp[((2*ly+1)*8 + 2*lx)*128 + c] + sp[((2*ly+1)*8 + 2*lx+1)*128 + c]);
        s1[u] = v;
        g_pyr1[(((size_t)t * 48 + gy*4 + ly) * 64 + gx*4 + lx) * LATC + c] = v;
    }
    __syncthreads();
#pragma unroll
    for (int k = 0; k < 2; k++) {
        int u = k * 256 + tid;
        int c = u & 127, pix = u >> 7;
        int ly = pix >> 1, lx = pix & 1;
        float v = 0.25f * (s1[((2*ly)*4 + 2*lx)*128 + c] + s1[((2*ly)*4 + 2*lx+1)*128 + c]
                         + s1[((2*ly+1)*4 + 2*lx)*128 + c] + s1[((2*ly+1)*4 + 2*lx+1)*128 + c]);
        s2[u] = v;
        g_pyr2[(((size_t)t * 24 + gy*2 + ly) * 32 + gx*2 + lx) * LATC + c] = v;
    }
    __syncthreads();
    if (tid < 128) {
        float v = 0.25f * (s2[tid] + s2[128 + tid] + s2[256 + tid] + s2[384 + tid]);
        g_pyr3[(((size_t)t * 12 + gy) * 16 + gx) * LATC + tid] = v;
    }
}

// ---------------------------------------------------------------------------
// Template features -> bf16 [l][n][p][c]
// ---------------------------------------------------------------------------
__global__ __launch_bounds__(128) void k_template(const float* __restrict__ q) {
    int n = blockIdx.x, l = blockIdx.y, c = threadIdx.x;
    int Hl, Wl;
    const float* fm = level_ptr(l, Hl, Wl);
    float qf = q[n * 3 + 0];
    float inv = exp2f(-(float)l) * 0.25f;
    float cx = q[n * 3 + 1] * inv, cy = q[n * 3 + 2] * inv;
    float tpos = fminf(fmaxf(qf, 0.f), (float)(TT - 1));
    int t0 = (int)floorf(tpos);
    float wt = tpos - (float)t0;
    int t1 = min(t0 + 1, TT - 1);
    const float* f0 = fm + (size_t)t0 * Hl * Wl * LATC;
    const float* f1 = fm + (size_t)t1 * Hl * Wl * LATC;
    __nv_bfloat16* dst = g_tf + (((size_t)l * NQ + n) * PP) * LATC + c;
    for (int p = 0; p < PP; p++) {
        int h = p / RR, ww = p % RR;
        float px = fminf(fmaxf(cx + (float)(h - 3), 0.f), (float)Wl - 1.f);
        float py = fminf(fmaxf(cy + (float)(ww - 3), 0.f), (float)Hl - 1.f);
        int x0 = (int)floorf(px); float wx = px - (float)x0; int x1 = min(x0 + 1, Wl - 1);
        int y0 = (int)floorf(py); float wy = py - (float)y0; int y1 = min(y0 + 1, Hl - 1);
        int o00 = (y0 * Wl + x0) * LATC + c, o01 = (y0 * Wl + x1) * LATC + c;
        int o10 = (y1 * Wl + x0) * LATC + c, o11 = (y1 * Wl + x1) * LATC + c;
        float v = (1.f - wy) * ((1.f - wx) * f0[o00] + wx * f0[o01])
                +        wy  * ((1.f - wx) * f0[o10] + wx * f0[o11]);
        if (wt > 0.f) {
            float v1 = (1.f - wy) * ((1.f - wx) * f1[o00] + wx * f1[o01])
                     +        wy  * ((1.f - wx) * f1[o10] + wx * f1[o11]);
            v = v * (1.f - wt) + v1 * wt;
        }
        dst[p * LATC] = __float2bfloat16(v);
    }
}

// ---------------------------------------------------------------------------
// Merged prep: 3 weight transposes + 2 pads + time-embedding interp
// ---------------------------------------------------------------------------
#define PR_W1 (HID * CV_K)
#define PR_W2 (EMB * HID)
#define PR_U1 (HID * X_K)
#define PR_CV ((4 * TT * NQ) * (CV_K - 2401))
#define PR_X  ((NQ * TT) * (X_K - D_IN))
#define PR_TE (TT * D_IN)
#define PR_ALL (PR_W1 + PR_W2 + PR_U1 + PR_CV + PR_X + PR_TE)

__global__ void k_prep(const float* __restrict__ fc1_w,
                       const float* __restrict__ fc2_w,
                       const float* __restrict__ up_w1,
                       const float* __restrict__ emb) {
    int i = blockIdx.x * blockDim.x + threadIdx.x;
    if (i < PR_W1) {
        int n = i / CV_K, k = i - n * CV_K;
        g_w1t[i] = __float2bfloat16((k < 2401) ? fc1_w[(size_t)k * HID + n] : 0.f);
        return;
    }
    i -= PR_W1;
    if (i < PR_W2) {
        int n = i / HID, k = i - n * HID;
        g_w2t[i] = __float2bfloat16(fc2_w[(size_t)k * EMB + n]);
        return;
    }
    i -= PR_W2;
    if (i < PR_U1) {
        int n = i / X_K, k = i - n * X_K;
        g_u1t[i] = __float2bfloat16((k < D_IN) ? up_w1[(size_t)k * HID + n] : 0.f);
        return;
    }
    i -= PR_U1;
    if (i < PR_CV) {
        int cw = CV_K - 2401;
        int r = i / cw, c = i - r * cw;
        g_cv[(size_t)r * CV_K + 2401 + c] = __float2bfloat16(0.f);
        return;
    }
    i -= PR_CV;
    if (i < PR_X) {
        int cw = X_K - D_IN;
        int r = i / cw, c = i - r * cw;
        g_x[(size_t)r * X_K + D_IN + c] = __float2bfloat16(0.f);
        return;
    }
    i -= PR_X;
    if (i < PR_TE) {
        int t = i / D_IN, d = i % D_IN;
        float j = ((float)t + 0.5f) * (50.f / 16.f) - 0.5f;
        j = fminf(fmaxf(j, 0.f), 49.f);
        int j0 = (int)floorf(j);
        int j1 = min(j0 + 1, 49);
        float w = j - (float)j0;
        g_te[i] = emb[j0 * D_IN + d] * (1.f - w) + emb[j1 * D_IN + d] * w;
    }
}

// ---------------------------------------------------------------------------
// Fused bilinear sample + 49x49x128 correlation via mma.sync.
// R9 gather + MMA, smem-staged coalesced epilogue store.
// ---------------------------------------------------------------------------
#define CS 136

__global__ __launch_bounds__(256) void k_corr_mma() {
    __shared__ __nv_bfloat16 cf[64 * CS];
    __shared__ __nv_bfloat16 tf[64 * CS];
    __shared__ __nv_bfloat16 stage[2408];
    __shared__ int   sO[PP][4];
    __shared__ float sW[PP][2];
    int n = blockIdx.x, t = blockIdx.y, l = blockIdx.z;
    int tid = threadIdx.x, lane = tid & 31, w = tid >> 5;
    int Hl, Wl;
    const float* fm = level_ptr(l, Hl, Wl);
    fm += (size_t)t * Hl * Wl * LATC;

    if (tid < PP) {
        float inv = exp2f(-(float)l);
        float cx = g_coords[(t * NQ + n) * 2 + 0] * inv;
        float cy = g_coords[(t * NQ + n) * 2 + 1] * inv;
        int h = tid / RR, ww = tid % RR;
        float px = fminf(fmaxf(cx + (float)(h - 3), 0.f), (float)Wl - 1.f);
        float py = fminf(fmaxf(cy + (float)(ww - 3), 0.f), (float)Hl - 1.f);
        int x0 = (int)floorf(px); float wx = px - (float)x0; int x1 = min(x0 + 1, Wl - 1);
        int y0 = (int)floorf(py); float wy = py - (float)y0; int y1 = min(y0 + 1, Hl - 1);
        sO[tid][0] = (y0 * Wl + x0) * LATC;
        sO[tid][1] = (y0 * Wl + x1) * LATC;
        sO[tid][2] = (y1 * Wl + x0) * LATC;
        sO[tid][3] = (y1 * Wl + x1) * LATC;
        sW[tid][0] = wx; sW[tid][1] = wy;
    }
    for (int i = tid; i < 15 * CS; i += 256) {
        cf[49 * CS + i] = __float2bfloat16(0.f);
        tf[49 * CS + i] = __float2bfloat16(0.f);
    }
    const __nv_bfloat16* tfg = g_tf + (((size_t)l * NQ + n) * PP) * LATC;
    for (int i = tid; i < PP * 16; i += 256) {
        int p = i >> 4, c8 = (i & 15) << 3;
        *(uint4*)&tf[p * CS + c8] = *(const uint4*)(tfg + p * LATC + c8);
    }
    __syncthreads();
    for (int i = tid; i < PP * 32; i += 256) {
        int p = i >> 5, c4 = (i & 31) << 2;
        float wx = sW[p][0], wy = sW[p][1];
        float w00 = (1.f - wy) * (1.f - wx), w01 = (1.f - wy) * wx;
        float w10 = wy * (1.f - wx),         w11 = wy * wx;
        float4 v00 = *(const float4*)(fm + sO[p][0] + c4);
        float4 v01 = *(const float4*)(fm + sO[p][1] + c4);
        float4 v10 = *(const float4*)(fm + sO[p][2] + c4);
        float4 v11 = *(const float4*)(fm + sO[p][3] + c4);
        float r0 = w00 * v00.x + w01 * v01.x + w10 * v10.x + w11 * v11.x;
        float r1 = w00 * v00.y + w01 * v01.y + w10 * v10.y + w11 * v11.y;
        float r2 = w00 * v00.z + w01 * v01.z + w10 * v10.z + w11 * v11.z;
        float r3 = w00 * v00.w + w01 * v01.w + w10 * v10.w + w11 * v11.w;
        __nv_bfloat162* dst = (__nv_bfloat162*)&cf[p * CS + c4];
        dst[0] = __floats2bfloat162_rn(r0, r1);
        dst[1] = __floats2bfloat162_rn(r2, r3);
    }
    __syncthreads();

    int m2 = w >> 2, nw = w & 3;
    float acc[2][2][4] = {};
#pragma unroll
    for (int ks = 0; ks < 8; ks++) {
        uint32_t b[2][2];
        {
            uint32_t rr[4];
            uint32_t addr = smem_u32(&tf[((nw << 4) + ((lane >> 4) << 3) + (lane & 7)) * CS
                                         + (ks << 4) + (((lane >> 3) & 1) << 3)]);
            ldsm4(rr, addr);
            b[0][0] = rr[0]; b[0][1] = rr[1]; b[1][0] = rr[2]; b[1][1] = rr[3];
        }
#pragma unroll
        for (int f = 0; f < 2; f++) {
            int fa = (m2 << 1) + f;
            uint32_t a[4];
            ldsm4(a, smem_u32(&cf[((fa << 4) + (lane & 15)) * CS + (ks << 4) + ((lane >> 4) << 3)]));
            mma_bf16(acc[f][0], a, b[0]);
            mma_bf16(acc[f][1], a, b[1]);
        }
    }

#pragma unroll
    for (int f = 0; f < 2; f++) {
        int m0 = ((m2 << 1) + f << 4) + (lane >> 2);
#pragma unroll
        for (int g = 0; g < 2; g++) {
            int nn = (nw << 4) + (g << 3) + ((lane & 3) << 1);
            if (nn < PP) {
                if (m0 < PP) stage[m0 * PP + nn] = __float2bfloat16(acc[f][g][0]);
                if (m0 + 8 < PP) stage[(m0 + 8) * PP + nn] = __float2bfloat16(acc[f][g][2]);
                if (nn + 1 < PP) {
                    if (m0 < PP) stage[m0 * PP + nn + 1] = __float2bfloat16(acc[f][g][1]);
                    if (m0 + 8 < PP) stage[(m0 + 8) * PP + nn + 1] = __float2bfloat16(acc[f][g][3]);
                }
            }
        }
    }
    __syncthreads();
    __nv_bfloat16* cv = g_cv + ((size_t)((l * TT + t) * NQ + n)) * CV_K;
    for (int i = tid; i < 300; i += 256)
        *(uint4*)(cv + (i << 3)) = *(const uint4*)(stage + (i << 3));
    if (tid == 0) cv[2400] = stage[2400];
}

// ---------------------------------------------------------------------------
// bf16 mma.sync GEMM, 128x128 CTA tile, LDG->compute->STS pipeline.
// mode: 0 = fp32 out, 1 = bf16 out, 2 = fused write into g_x corr cols (+te)
// ---------------------------------------------------------------------------
#define GST 40

__global__ __launch_bounds__(256) void k_gemm_bf(const __nv_bfloat16* __restrict__ A,
                                                 const __nv_bfloat16* __restrict__ Bt,
                                                 const float* __restrict__ bias,
                                                 void* __restrict__ Cv,
                                                 int M, int N, int K, int act, int mode) {
    __shared__ __nv_bfloat16 As[2][128 * GST];
    __shared__ __nv_bfloat16 Bs[2][128 * GST];
    int tid = threadIdx.x, lane = tid & 31, warp = tid >> 5;
    int wm = (warp & 1) << 6, wn = (warp >> 1) << 5;
    int row0 = blockIdx.y << 7, col0 = blockIdx.x << 7;
    const __nv_bfloat16* Ag = A  + (size_t)row0 * K;
    const __nv_bfloat16* Bg = Bt + (size_t)col0 * K;

    int r1 = tid >> 2, c1 = (tid & 3) << 3;
    int r2 = (tid + 256) >> 2, c2 = ((tid + 256) & 3) << 3;

    *(uint4*)(As[0] + r1 * GST + c1) = *(const uint4*)(Ag + (size_t)r1 * K + c1);
    *(uint4*)(As[0] + r2 * GST + c2) = *(const uint4*)(Ag + (size_t)r2 * K + c2);
    *(uint4*)(Bs[0] + r1 * GST + c1) = *(const uint4*)(Bg + (size_t)r1 * K + c1);
    *(uint4*)(Bs[0] + r2 * GST + c2) = *(const uint4*)(Bg + (size_t)r2 * K + c2);
    __syncthreads();

    float acc[4][4][4] = {};
    int nk = K >> 5;
    for (int i = 0; i < nk; i++) {
        int s = i & 1;
        uint4 ra0, ra1, rb0, rb1;
        bool pre = (i + 1 < nk);
        if (pre) {
            int k0 = (i + 1) << 5;
            ra0 = *(const uint4*)(Ag + (size_t)r1 * K + k0 + c1);
            ra1 = *(const uint4*)(Ag + (size_t)r2 * K + k0 + c2);
            rb0 = *(const uint4*)(Bg + (size_t)r1 * K + k0 + c1);
            rb1 = *(const uint4*)(Bg + (size_t)r2 * K + k0 + c2);
        }
#pragma unroll
        for (int ks = 0; ks < 2; ks++) {
            uint32_t b[4][2];
#pragma unroll
            for (int g = 0; g < 2; g++) {
                uint32_t rr[4];
                uint32_t addr = smem_u32(Bs[s] + (wn + (g << 4) + ((lane >> 4) << 3) + (lane & 7)) * GST
                                         + (ks << 4) + (((lane >> 3) & 1) << 3));
                ldsm4(rr, addr);
                b[g * 2][0] = rr[0]; b[g * 2][1] = rr[1];
                b[g * 2 + 1][0] = rr[2]; b[g * 2 + 1][1] = rr[3];
            }
#pragma unroll
            for (int f = 0; f < 4; f++) {
                uint32_t a[4];
                ldsm4(a, smem_u32(As[s] + (wm + (f << 4) + (lane & 15)) * GST
                                  + (ks << 4) + ((lane >> 4) << 3)));
#pragma unroll
                for (int g = 0; g < 4; g++) mma_bf16(acc[f][g], a, b[g]);
            }
        }
        if (pre) {
            int s2 = s ^ 1;
            *(uint4*)(As[s2] + r1 * GST + c1) = ra0;
            *(uint4*)(As[s2] + r2 * GST + c2) = ra1;
            *(uint4*)(Bs[s2] + r1 * GST + c1) = rb0;
            *(uint4*)(Bs[s2] + r2 * GST + c2) = rb1;
        }
        __syncthreads();
    }
#pragma unroll
    for (int f = 0; f < 4; f++) {
        int m = row0 + wm + (f << 4) + (lane >> 2);
#pragma unroll
        for (int g = 0; g < 4; g++) {
            int nn = col0 + wn + (g << 3) + ((lane & 3) << 1);
            float b0 = bias[nn], b1 = bias[nn + 1];
            float v0 = acc[f][g][0] + b0, v1 = acc[f][g][1] + b1;
            float v2 = acc[f][g][2] + b0, v3 = acc[f][g][3] + b1;
            if (act) { v0 = geluf(v0); v1 = geluf(v1); v2 = geluf(v2); v3 = geluf(v3); }
            if (mode == 1) {
                __nv_bfloat16* C = (__nv_bfloat16*)Cv;
                C[(size_t)m * N + nn] = __float2bfloat16(v0);
                C[(size_t)m * N + nn + 1] = __float2bfloat16(v1);
                C[(size_t)(m + 8) * N + nn] = __float2bfloat16(v2);
                C[(size_t)(m + 8) * N + nn + 1] = __float2bfloat16(v3);
            } else if (mode == 0) {
                float* C = (float*)Cv;
                C[(size_t)m * N + nn] = v0;
                C[(size_t)m * N + nn + 1] = v1;
                C[(size_t)(m + 8) * N + nn] = v2;
                C[(size_t)(m + 8) * N + nn + 1] = v3;
            } else {
                // mode 2: FC2 fused into g_x corr columns with te added.
                // m = (l*16+t)*128+n  -> x row = n*16+t, col = 2 + l*256 + nn
                int qn = m & 127, qt = (m >> 7) & 15, ql = m >> 11;
                int colx = 2 + (ql << 8) + nn;
                float t0 = g_te[qt * D_IN + colx], t1 = g_te[qt * D_IN + colx + 1];
                __nv_bfloat16* X = g_x + (size_t)((qn << 4) | qt) * X_K;
                X[colx]     = __float2bfloat16(v0 + t0);
                X[colx + 1] = __float2bfloat16(v1 + t1);
                int m8 = m + 8;
                int qn8 = m8 & 127, qt8 = (m8 >> 7) & 15, ql8 = m8 >> 11;
                int colx8 = 2 + (ql8 << 8) + nn;
                float t2 = g_te[qt8 * D_IN + colx8], t3 = g_te[qt8 * D_IN + colx8 + 1];
                __nv_bfloat16* X8 = g_x + (size_t)((qn8 << 4) | qt8) * X_K;
                X8[colx8]     = __float2bfloat16(v2 + t2);
                X8[colx8 + 1] = __float2bfloat16(v3 + t3);
            }
        }
    }
}

// ---------------------------------------------------------------------------
// bf16 mma.sync GEMM, 64x64 CTA tile (small-grid shapes: up-GEMM).
// ---------------------------------------------------------------------------
__global__ __launch_bounds__(128) void k_gemm64(const __nv_bfloat16* __restrict__ A,
                                                const __nv_bfloat16* __restrict__ Bt,
                                                const float* __restrict__ bias,
                                                void* __restrict__ Cv,
                                                int M, int N, int K, int act, int outbf) {
    __shared__ __nv_bfloat16 As[2][64 * GST];
    __shared__ __nv_bfloat16 Bs[2][64 * GST];
    int tid = threadIdx.x, lane = tid & 31, warp = tid >> 5;
    int wm = (warp & 1) << 5, wn = (warp >> 1) << 5;
    int row0 = blockIdx.y << 6, col0 = blockIdx.x << 6;
    const __nv_bfloat16* Ag = A  + (size_t)row0 * K;
    const __nv_bfloat16* Bg = Bt + (size_t)col0 * K;

    int r1 = tid >> 2, c1 = (tid & 3) << 3;
    int r2 = (tid + 128) >> 2, c2 = ((tid + 128) & 3) << 3;

    *(uint4*)(As[0] + r1 * GST + c1) = *(const uint4*)(Ag + (size_t)r1 * K + c1);
    *(uint4*)(As[0] + r2 * GST + c2) = *(const uint4*)(Ag + (size_t)r2 * K + c2);
    *(uint4*)(Bs[0] + r1 * GST + c1) = *(const uint4*)(Bg + (size_t)r1 * K + c1);
    *(uint4*)(Bs[0] + r2 * GST + c2) = *(const uint4*)(Bg + (size_t)r2 * K + c2);
    __syncthreads();

    float acc[2][4][4] = {};
    int nk = K >> 5;
    for (int i = 0; i < nk; i++) {
        int s = i & 1;
        uint4 ra0, ra1, rb0, rb1;
        bool pre = (i + 1 < nk);
        if (pre) {
            int k0 = (i + 1) << 5;
            ra0 = *(const uint4*)(Ag + (size_t)r1 * K + k0 + c1);
            ra1 = *(const uint4*)(Ag + (size_t)r2 * K + k0 + c2);
            rb0 = *(const uint4*)(Bg + (size_t)r1 * K + k0 + c1);
            rb1 = *(const uint4*)(Bg + (size_t)r2 * K + k0 + c2);
        }
#pragma unroll
        for (int ks = 0; ks < 2; ks++) {
            uint32_t b[4][2];
#pragma unroll
            for (int g = 0; g < 2; g++) {
                uint32_t rr[4];
                uint32_t addr = smem_u32(Bs[s] + (wn + (g << 4) + ((lane >> 4) << 3) + (lane & 7)) * GST
                                         + (ks << 4) + (((lane >> 3) & 1) << 3));
                ldsm4(rr, addr);
                b[g * 2][0] = rr[0]; b[g * 2][1] = rr[1];
                b[g * 2 + 1][0] = rr[2]; b[g * 2 + 1][1] = rr[3];
            }
#pragma unroll
            for (int f = 0; f < 2; f++) {
                uint32_t a[4];
                ldsm4(a, smem_u32(As[s] + (wm + (f << 4) + (lane & 15)) * GST
                                  + (ks << 4) + ((lane >> 4) << 3)));
#pragma unroll
                for (int g = 0; g < 4; g++) mma_bf16(acc[f][g], a, b[g]);
            }
        }
        if (pre) {
            int s2 = s ^ 1;
            *(uint4*)(As[s2] + r1 * GST + c1) = ra0;
            *(uint4*)(As[s2] + r2 * GST + c2) = ra1;
            *(uint4*)(Bs[s2] + r1 * GST + c1) = rb0;
            *(uint4*)(Bs[s2] + r2 * GST + c2) = rb1;
        }
        __syncthreads();
    }
#pragma unroll
    for (int f = 0; f < 2; f++) {
        int m = row0 + wm + (f << 4) + (lane >> 2);
#pragma unroll
        for (int g = 0; g < 4; g++) {
            int nn = col0 + wn + (g << 3) + ((lane & 3) << 1);
            float b0 = bias[nn], b1 = bias[nn + 1];
            float v0 = acc[f][g][0] + b0, v1 = acc[f][g][1] + b1;
            float v2 = acc[f][g][2] + b0, v3 = acc[f][g][3] + b1;
            if (act) { v0 = geluf(v0); v1 = geluf(v1); v2 = geluf(v2); v3 = geluf(v3); }
            if (outbf) {
                __nv_bfloat16* C = (__nv_bfloat16*)Cv;
                C[(size_t)m * N + nn] = __float2bfloat16(v0);
                C[(size_t)m * N + nn + 1] = __float2bfloat16(v1);
                C[(size_t)(m + 8) * N + nn] = __float2bfloat16(v2);
                C[(size_t)(m + 8) * N + nn + 1] = __float2bfloat16(v3);
            } else {
                float* C = (float*)Cv;
                C[(size_t)m * N + nn] = v0;
                C[(size_t)m * N + nn + 1] = v1;
                C[(size_t)(m + 8) * N + nn] = v2;
                C[(size_t)(m + 8) * N + nn + 1] = v3;
            }
        }
    }
}

// ---------------------------------------------------------------------------
// Assemble: only non-corr dims of g_x (vis, conf, posenc) + te. 86 dims/row.
// ---------------------------------------------------------------------------
__global__ __launch_bounds__(128) void k_assemble() {
    int row = blockIdx.x;
    int n = row >> 4, t = row & 15;
    int tid = threadIdx.x;
    __shared__ float x4[4];
    if (tid == 0) {
        float cx = g_coords[(t * NQ + n) * 2 + 0];
        float cy = g_coords[(t * NQ + n) * 2 + 1];
        float rfx = 0.f, rfy = 0.f, rbx = 0.f, rby = 0.f;
        if (t < TT - 1) {
            rfx = (cx - g_coords[((t + 1) * NQ + n) * 2 + 0]) * (1.f / 128.f);
            rfy = (cy - g_coords[((t + 1) * NQ + n) * 2 + 1]) * (1.f / 96.f);
        }
        if (t > 0) {
            rbx = (cx - g_coords[((t - 1) * NQ + n) * 2 + 0]) * (1.f / 128.f);
            rby = (cy - g_coords[((t - 1) * NQ + n) * 2 + 1]) * (1.f / 96.f);
        }
        x4[0] = rfx; x4[1] = rfy; x4[2] = rbx; x4[3] = rby;
    }
    __syncthreads();
    if (tid >= 86) return;
    int d = (tid < 2) ? tid : 1024 + tid;   // 0,1, then 1026..1109
    float v;
    if (d == 0) v = g_vis[t * NQ + n];
    else if (d == 1) v = g_conf[t * NQ + n];
    else {
        int j = d - (2 + 4 * EMB);
        if (j < 4) v = x4[j];
        else if (j < 44) {
            int s = (j - 4) >> 2, dd = (j - 4) & 3;
            v = sinf(x4[dd] * exp2f((float)s));
        } else {
            int s = (j - 44) >> 2, dd = (j - 44) & 3;
            v = cosf(x4[dd] * exp2f((float)s));
        }
    }
    g_x[(size_t)row * X_K + d] = __float2bfloat16(v + g_te[t * D_IN + d]);
}

// ---------------------------------------------------------------------------
// Final tiny GEMV (384->4) + state update
// ---------------------------------------------------------------------------
__global__ __launch_bounds__(128) void k_update(const float* __restrict__ w2,
                                                const float* __restrict__ b2) {
    int row = blockIdx.x;
    int tid = threadIdx.x;
    const float* hrow = g_h2 + (size_t)row * HID;
    float a0 = 0.f, a1 = 0.f, a2 = 0.f, a3 = 0.f;
    for (int i = tid; i < HID; i += 128) {
        float h = hrow[i];
        const float* w = w2 + i * 4;
        a0 = fmaf(h, w[0], a0); a1 = fmaf(h, w[1], a1);
        a2 = fmaf(h, w[2], a2); a3 = fmaf(h, w[3], a3);
    }
#pragma unroll
    for (int o = 16; o; o >>= 1) {
        a0 += __shfl_xor_sync(0xffffffffu, a0, o);
        a1 += __shfl_xor_sync(0xffffffffu, a1, o);
        a2 += __shfl_xor_sync(0xffffffffu, a2, o);
        a3 += __shfl_xor_sync(0xffffffffu, a3, o);
    }
    __shared__ float red[4][4];
    int warp = tid >> 5, lane = tid & 31;
    if (lane == 0) { red[warp][0] = a0; red[warp][1] = a1; red[warp][2] = a2; red[warp][3] = a3; }
    __syncthreads();
    if (tid == 0) {
        float d0 = red[0][0] + red[1][0] + red[2][0] + red[3][0] + b2[0];
        float d1 = red[0][1] + red[1][1] + red[2][1] + red[3][1] + b2[1];
        float d2 = red[0][2] + red[1][2] + red[2][2] + red[3][2] + b2[2];
        float d3 = red[0][3] + red[1][3] + red[2][3] + red[3][3] + b2[3];
        int n = row >> 4, t = row & 15;
        g_coords[(t * NQ + n) * 2 + 0] += d0;
        g_coords[(t * NQ + n) * 2 + 1] += d1;
        g_vis[t * NQ + n]  += d2;
        g_conf[t * NQ + n] += d3;
    }
}

// ---------------------------------------------------------------------------
// Outputs
// ---------------------------------------------------------------------------
__global__ void k_output(float* __restrict__ out) {
    int i = blockIdx.x * blockDim.x + threadIdx.x;
    if (i >= 8192) return;
    if (i < 4096) out[i] = g_coords[i] * 4.f;
    else if (i < 6144) out[i] = 1.f / (1.f + expf(-g_vis[i - 4096]));
    else out[i] = 1.f / (1.f + expf(-g_conf[i - 6144]));
}

// ---------------------------------------------------------------------------
// Launch. Order: conv(1) pools(2) template(3) corr(4, profiled) prep(5) ...
// ---------------------------------------------------------------------------
extern "C" void kernel_launch(void* const* d_in, const int* in_sizes, int n_in,
                              void* d_out, int out_size) {
    const float* video   = (const float*)d_in[0];
    const float* queries = (const float*)d_in[1];
    const float* fnet_w  = (const float*)d_in[2];
    const float* fnet_b  = (const float*)d_in[3];
    const float* fc1_w   = (const float*)d_in[4];
    const float* fc1_b   = (const float*)d_in[5];
    const float* fc2_w   = (const float*)d_in[6];
    const float* fc2_b   = (const float*)d_in[7];
    const float* up_w1   = (const float*)d_in[8];
    const float* up_b1   = (const float*)d_in[9];
    const float* up_w2   = (const float*)d_in[10];
    const float* up_b2   = (const float*)d_in[11];
    const float* time_emb= (const float*)d_in[12];
    float* out = (float*)d_out;

    cudaFuncSetAttribute(k_conv_tc, cudaFuncAttributeMaxDynamicSharedMemorySize, CONV_SMEM);

    __nv_bfloat16 *p_cv, *p_h1, *p_x, *p_w1t, *p_w2t, *p_u1t;
    float *p_h2;
    cudaGetSymbolAddress((void**)&p_cv,  g_cv);
    cudaGetSymbolAddress((void**)&p_h1,  g_h1);
    cudaGetSymbolAddress((void**)&p_x,   g_x);
    cudaGetSymbolAddress((void**)&p_h2,  g_h2);
    cudaGetSymbolAddress((void**)&p_w1t, g_w1t);
    cudaGetSymbolAddress((void**)&p_w2t, g_w2t);
    cudaGetSymbolAddress((void**)&p_u1t, g_u1t);

    const int M1 = 4 * TT * NQ;   // 8192
    const int M3 = NQ * TT;       // 2048

    k_conv_tc<<<TT * 96, 256, CONV_SMEM>>>(video, fnet_w, fnet_b, queries);  // 1
    k_pools<<<TT * 12 * 16, 256>>>();                                        // 2
    k_template<<<dim3(NQ, 4), 128>>>(queries);                               // 3

    for (int it = 0; it < 4; it++) {
        k_corr_mma<<<dim3(NQ, TT, 4), 256>>>();                              // 4 on it=0
        if (it == 0)
            k_prep<<<(PR_ALL + 255) / 256, 256>>>(fc1_w, fc2_w, up_w1, time_emb);
        k_gemm_bf<<<dim3(HID / 128, M1 / 128), 256>>>(p_cv, p_w1t, fc1_b, p_h1, M1, HID, CV_K, 1, 1);
        k_gemm_bf<<<dim3(EMB / 128, M1 / 128), 256>>>(p_h1, p_w2t, fc2_b, p_x, M1, EMB, HID, 0, 2);
        k_assemble<<<M3, 128>>>();
        k_gemm64<<<dim3(HID / 64, M3 / 64), 128>>>(p_x, p_u1t, up_b1, p_h2, M3, HID, X_K, 1, 0);
        k_update<<<M3, 128>>>(up_w2, up_b2);
    }
    k_output<<<(8192 + 255) / 256, 256>>>(out);
}